// round 14
// baseline (speedup 1.0000x reference)
#include <cuda_runtime.h>
#include <cuda_bf16.h>
#include <math.h>
#include <stdint.h>

#define BB 2
#define NTOK 16384
#define IND 1536
#define DD 512
#define NH 8
#define DH 64
#define LM 256
#define LCH 65
#define NPD 16640
#define NC 16385
#define PADN 255
#define D3 1536
#define QSCALE 0.125f
#define NSPL 10
#define KCH 1664    // NPD / NSPL

constexpr long SZ_H   = (long)BB*NC*DD;
constexpr long SZ_QKV = (long)BB*NPD*D3;
constexpr long SZ_OH  = (long)BB*NH*NPD*DH;
constexpr long SZ_MM  = 16L*LM*LM;
constexpr long SZ_SV  = 16L*LM*DH;

constexpr long OFF_H    = 0;
constexpr long OFF_MUR  = OFF_H    + SZ_H;        // per-row (mu, rstd): BB*NC*2
constexpr long OFF_QKV  = OFF_MUR  + (long)BB*NC*2;
constexpr long OFF_AOUT = OFF_QKV  + SZ_QKV;
constexpr long OFF_H2   = OFF_AOUT + (long)BB*NPD*DD;
constexpr long OFF_QL   = OFF_H2   + SZ_H;
constexpr long OFF_KL   = OFF_QL   + SZ_SV;
constexpr long OFF_A2   = OFF_KL   + SZ_SV;
constexpr long OFF_Z0   = OFF_A2   + SZ_MM;
constexpr long OFF_Z1   = OFF_Z0   + SZ_MM;
constexpr long OFF_XZ   = OFF_Z1   + SZ_MM;
constexpr long OFF_T1   = OFF_XZ   + SZ_MM;
constexpr long OFF_T2   = OFF_T1   + SZ_MM;
constexpr long OFF_AV   = OFF_T2   + SZ_MM;
constexpr long OFF_ZAV  = OFF_AV   + SZ_SV;
constexpr long OFF_WT   = OFF_ZAV  + SZ_SV;
constexpr long OFF_AVP  = OFF_WT   + 49L*DD;
constexpr long OFF_SC   = OFF_AVP  + 16L*NSPL*LM*DH;
constexpr long OFF_M3   = OFF_SC   + 16;
constexpr long OFF_S3   = OFF_M3   + 16L*NSPL*LM;
constexpr long OFF_WBF  = OFF_S3   + 16L*NSPL*LM;
constexpr long WBF_FLOATS = 2900000;
constexpr long TOTAL_F  = OFF_WBF + WBF_FLOATS;

__device__ __align__(256) float g_buf[TOTAL_F];

constexpr long WB_T1   = 0;
constexpr long WB_QKV1 = WB_T1   + 2L*512*1536;
constexpr long WB_QKV2 = WB_QKV1 + 2L*512*1536;
constexpr long WB_OUT1 = WB_QKV2 + 2L*512*1536;
constexpr long WB_OUT2 = WB_OUT1 + 2L*512*512;

// ---------------- mma.sync m16n8k16 bf16 + ldmatrix ----------------
__device__ __forceinline__ void mma16816(float* c, const uint32_t* a, const uint32_t* b) {
    asm volatile(
        "mma.sync.aligned.m16n8k16.row.col.f32.bf16.bf16.f32 "
        "{%0,%1,%2,%3}, {%4,%5,%6,%7}, {%8,%9}, {%0,%1,%2,%3};"
        : "+f"(c[0]), "+f"(c[1]), "+f"(c[2]), "+f"(c[3])
        : "r"(a[0]), "r"(a[1]), "r"(a[2]), "r"(a[3]), "r"(b[0]), "r"(b[1]));
}
__device__ __forceinline__ void ldsm4(uint32_t& r0, uint32_t& r1, uint32_t& r2, uint32_t& r3,
                                      const void* p) {
    uint32_t a = (uint32_t)__cvta_generic_to_shared(p);
    asm volatile("ldmatrix.sync.aligned.m8n8.x4.shared.b16 {%0,%1,%2,%3}, [%4];"
        : "=r"(r0), "=r"(r1), "=r"(r2), "=r"(r3) : "r"(a));
}
__device__ __forceinline__ void ldsm4t(uint32_t& r0, uint32_t& r1, uint32_t& r2, uint32_t& r3,
                                       const void* p) {
    uint32_t a = (uint32_t)__cvta_generic_to_shared(p);
    asm volatile("ldmatrix.sync.aligned.m8n8.x4.trans.shared.b16 {%0,%1,%2,%3}, [%4];"
        : "=r"(r0), "=r"(r1), "=r"(r2), "=r"(r3) : "r"(a));
}
__device__ __forceinline__ void split2(float x0, float x1, uint32_t& hi, uint32_t& lo) {
    __nv_bfloat16 h0 = __float2bfloat16(x0), h1 = __float2bfloat16(x1);
    __nv_bfloat16 l0 = __float2bfloat16(x0 - __bfloat162float(h0));
    __nv_bfloat16 l1 = __float2bfloat16(x1 - __bfloat162float(h1));
    __nv_bfloat162 hh = __halves2bfloat162(h0, h1);
    __nv_bfloat162 ll = __halves2bfloat162(l0, l1);
    hi = *(uint32_t*)&hh; lo = *(uint32_t*)&ll;
}
__device__ __forceinline__ float brsum(float v, float* shm) {
    int lane = threadIdx.x & 31, wid = threadIdx.x >> 5;
#pragma unroll
    for (int o = 16; o; o >>= 1) v += __shfl_xor_sync(0xffffffffu, v, o);
    __syncthreads();
    if (lane == 0) shm[wid] = v;
    __syncthreads();
    int nw = blockDim.x >> 5;
    float r = (threadIdx.x < nw) ? shm[threadIdx.x] : 0.f;
    if (wid == 0) {
#pragma unroll
        for (int o = 16; o; o >>= 1) r += __shfl_xor_sync(0xffffffffu, r, o);
        if (lane == 0) shm[0] = r;
    }
    __syncthreads();
    return shm[0];
}

// ============ weight GEMM: C = A[M,K] @ W[K,N] ============
// LNA: A = H (NC rows); logical row rr maps to H row rr-PADN, pads are exact zeros,
//      affine (x-mu)*rstd*g[col]+b[col] applied in the loader.
// RESID: C = H, rows >= PADN accumulate (fused residual).
template<bool BIASF, bool RELUF, bool RESID, bool LNA>
__global__ void __launch_bounds__(256)
tgemm(const float* __restrict__ A, const __nv_bfloat16* __restrict__ Wh,
      const __nv_bfloat16* __restrict__ Wl, const float* __restrict__ bias,
      float* __restrict__ C, int K, int lda, int ldc, long sAb, long sCb,
      const float* __restrict__ lng, const float* __restrict__ lnb,
      const float* __restrict__ mur)
{
    __shared__ __nv_bfloat16 Ah[128][40], Al[128][40], Bh[128][40], Bl[128][40];
    const int tid = threadIdx.x, warp = tid >> 5, lane = tid & 31;
    const int rowBase = blockIdx.y << 7, colBase = blockIdx.x << 7;
    A += (long)blockIdx.z * sAb;
    C += (long)blockIdx.z * sCb;
    const int lr = tid >> 1, lh = (tid & 1) << 4;
    bool valid = true;
    float mu = 0.f, rstd = 0.f;
    const float* Ap;
    if (LNA) {
        int rr = rowBase + lr;
        valid = rr >= PADN;
        long hrow = valid ? (long)(rr - PADN) : 0;
        Ap = A + hrow * lda + lh;
        const float* mr = mur + ((long)blockIdx.z * NC + hrow) * 2;
        mu = mr[0]; rstd = mr[1];
    } else {
        Ap = A + (long)(rowBase + lr) * lda + lh;
    }
    const __nv_bfloat16* Bhp = Wh + (long)(colBase + lr) * K + lh;
    const __nv_bfloat16* Blp = Wl + (long)(colBase + lr) * K + lh;
    const int wm = (warp & 1) << 6, wn = (warp >> 1) << 5;
    const int gr = lane >> 2;
    const int a_r = (lane & 7) + ((lane >> 3) & 1) * 8;
    const int a_c = (lane >> 4) << 3;
    const int b_r = lane & 7;
    const int b_nj = (lane >> 4) & 1;
    const int b_c = ((lane >> 3) & 1) << 3;

    float acc[4][4][4];
#pragma unroll
    for (int i = 0; i < 4; i++)
#pragma unroll
        for (int j = 0; j < 4; j++)
#pragma unroll
            for (int t = 0; t < 4; t++) acc[i][j][t] = 0.f;

    float fa[16];
    uint4 vbh0, vbh1, vbl0, vbl1;
#pragma unroll
    for (int i = 0; i < 4; i++) {
        float4 v = *(const float4*)(Ap + i * 4);
        fa[i*4+0] = v.x; fa[i*4+1] = v.y; fa[i*4+2] = v.z; fa[i*4+3] = v.w;
    }
    vbh0 = *(const uint4*)(Bhp); vbh1 = *(const uint4*)(Bhp + 8);
    vbl0 = *(const uint4*)(Blp); vbl1 = *(const uint4*)(Blp + 8);

    const int nch = K >> 5;
    for (int c = 0; c < nch; c++) {
#pragma unroll
        for (int i = 0; i < 8; i++) {
            float x0 = fa[2*i], x1 = fa[2*i+1];
            if (LNA) {
                int col = c * 32 + lh + 2*i;
                float2 gg = *(const float2*)(lng + col);
                float2 bb = *(const float2*)(lnb + col);
                x0 = valid ? (x0 - mu) * rstd * gg.x + bb.x : 0.f;
                x1 = valid ? (x1 - mu) * rstd * gg.y + bb.y : 0.f;
            }
            uint32_t hi, lo;
            split2(x0, x1, hi, lo);
            *(uint32_t*)&Ah[lr][lh + 2*i] = hi;
            *(uint32_t*)&Al[lr][lh + 2*i] = lo;
        }
        *(uint4*)&Bh[lr][lh]     = vbh0; *(uint4*)&Bh[lr][lh + 8] = vbh1;
        *(uint4*)&Bl[lr][lh]     = vbl0; *(uint4*)&Bl[lr][lh + 8] = vbl1;
        __syncthreads();
        if (c + 1 < nch) {
            const float* ap = Ap + (c + 1) * 32;
#pragma unroll
            for (int i = 0; i < 4; i++) {
                float4 v = *(const float4*)(ap + i * 4);
                fa[i*4+0] = v.x; fa[i*4+1] = v.y; fa[i*4+2] = v.z; fa[i*4+3] = v.w;
            }
            const __nv_bfloat16* bp = Bhp + (c + 1) * 32;
            const __nv_bfloat16* lp = Blp + (c + 1) * 32;
            vbh0 = *(const uint4*)(bp); vbh1 = *(const uint4*)(bp + 8);
            vbl0 = *(const uint4*)(lp); vbl1 = *(const uint4*)(lp + 8);
        }
#pragma unroll
        for (int s = 0; s < 2; s++) {
            const int k16 = s * 16;
            uint32_t bhf[4][2], blf[4][2];
#pragma unroll
            for (int njp = 0; njp < 2; njp++) {
                int n = wn + (njp * 2 + b_nj) * 8 + b_r;
                ldsm4(bhf[njp*2][0], bhf[njp*2][1], bhf[njp*2+1][0], bhf[njp*2+1][1],
                      &Bh[n][k16 + b_c]);
                ldsm4(blf[njp*2][0], blf[njp*2][1], blf[njp*2+1][0], blf[njp*2+1][1],
                      &Bl[n][k16 + b_c]);
            }
#pragma unroll
            for (int mi = 0; mi < 4; mi++) {
                int r = wm + mi * 16 + a_r;
                uint32_t ah[4], al[4];
                ldsm4(ah[0], ah[1], ah[2], ah[3], &Ah[r][k16 + a_c]);
                ldsm4(al[0], al[1], al[2], al[3], &Al[r][k16 + a_c]);
#pragma unroll
                for (int nj = 0; nj < 4; nj++) {
                    mma16816(acc[mi][nj], ah, bhf[nj]);
                    mma16816(acc[mi][nj], ah, blf[nj]);
                    mma16816(acc[mi][nj], al, bhf[nj]);
                }
            }
        }
        __syncthreads();
    }

#pragma unroll
    for (int mi = 0; mi < 4; mi++) {
        int row = rowBase + wm + mi * 16 + gr;
#pragma unroll
        for (int nj = 0; nj < 4; nj++) {
            int col = colBase + wn + nj * 8 + (lane & 3) * 2;
            float v0 = acc[mi][nj][0], v1 = acc[mi][nj][1];
            float v2 = acc[mi][nj][2], v3 = acc[mi][nj][3];
            if (BIASF) {
                float b0 = __ldg(bias + col), b1 = __ldg(bias + col + 1);
                v0 += b0; v1 += b1; v2 += b0; v3 += b1;
            }
            if (RELUF) {
                v0 = fmaxf(v0, 0.f); v1 = fmaxf(v1, 0.f);
                v2 = fmaxf(v2, 0.f); v3 = fmaxf(v3, 0.f);
            }
            if (RESID) {
                if (row >= PADN) {
                    float* a0 = C + (long)(row - PADN) * ldc + col;
                    float2 o = *(float2*)a0;
                    *(float2*)a0 = make_float2(v0 + o.x, v1 + o.y);
                }
                if (row + 8 >= PADN) {
                    float* a1 = C + (long)(row + 8 - PADN) * ldc + col;
                    float2 o = *(float2*)a1;
                    *(float2*)a1 = make_float2(v2 + o.x, v3 + o.y);
                }
            } else {
                *(float2*)(C + (long)row * ldc + col)       = make_float2(v0, v1);
                *(float2*)(C + (long)(row + 8) * ldc + col) = make_float2(v2, v3);
            }
        }
    }
}

template<bool BI, bool RE, bool RD, bool LN>
static void TG(const float* A, const __nv_bfloat16* wb, const float* bias, float* C,
               int M, int N, int K, int lda, int ldc, long sAb, long sCb, int nbz,
               const float* lng = nullptr, const float* lnb = nullptr,
               const float* mur = nullptr)
{
    dim3 g(N >> 7, M >> 7, nbz);
    tgemm<BI, RE, RD, LN><<<g, 256>>>(A, wb, wb + (long)N * K, bias, C, K, lda, ldc,
                                      sAb, sCb, lng, lnb, mur);
}

// ============ natural-layout GEMM (pinv/ZAV): C = alpha*A@B + diag*I ============
template<int BN>
__global__ void __launch_bounds__(256)
tg3(const float* __restrict__ A, const float* __restrict__ B, float* __restrict__ C,
    float* __restrict__ C2, int K, int lda, int ldb, int ldc,
    long sA1, long sB1, long sC,
    float alpha, float addDiag, float alpha2, float diag2)
{
    __shared__ __nv_bfloat16 Ah[64][40], Al[64][40];
    __shared__ __nv_bfloat16 Bkh[32][BN + 8], Bkl[32][BN + 8];
    const int tid = threadIdx.x, warp = tid >> 5, lane = tid & 31;
    int z = blockIdx.z;
    A += (long)z * sA1;
    B += (long)z * sB1;
    C += (long)z * sC;
    if (C2) C2 += (long)z * sC;
    const int rowBase = blockIdx.y << 6, colBase = blockIdx.x * BN;
    const int lr = tid >> 2, lh = (tid & 3) << 3;
    const float* Ap = A + (long)(rowBase + lr) * lda + lh;
    constexpr int BNV = BN / 8;
    const int bkr = tid >> 3, bn0 = (tid & 7) * BNV;
    const float* Bp = B + (long)bkr * ldb + colBase + bn0;
    constexpr int NJ = BN / 32;
    const int wm = (warp & 1) << 5, wn = (warp >> 1) * (BN / 4);
    const int gr = lane >> 2;
    const int a_r = (lane & 7) + ((lane >> 3) & 1) * 8, a_c = (lane >> 4) << 3;
    const int b_kr = (lane & 7) + ((lane >> 3) & 1) * 8, b_nc = (lane >> 4) << 3;

    float acc[2][NJ][4];
#pragma unroll
    for (int i = 0; i < 2; i++)
#pragma unroll
        for (int j = 0; j < NJ; j++)
#pragma unroll
            for (int t = 0; t < 4; t++) acc[i][j][t] = 0.f;

    float fa[8], fb[BNV];
#pragma unroll
    for (int i = 0; i < 2; i++) {
        float4 v = *(const float4*)(Ap + i * 4);
        fa[i*4+0] = v.x; fa[i*4+1] = v.y; fa[i*4+2] = v.z; fa[i*4+3] = v.w;
    }
#pragma unroll
    for (int i = 0; i < BNV / 4; i++) {
        float4 v = *(const float4*)(Bp + i * 4);
        fb[i*4+0] = v.x; fb[i*4+1] = v.y; fb[i*4+2] = v.z; fb[i*4+3] = v.w;
    }

    const int nch = K >> 5;
    for (int c = 0; c < nch; c++) {
#pragma unroll
        for (int i = 0; i < 4; i++) {
            uint32_t hi, lo;
            split2(fa[2*i], fa[2*i+1], hi, lo);
            *(uint32_t*)&Ah[lr][lh + 2*i] = hi;
            *(uint32_t*)&Al[lr][lh + 2*i] = lo;
        }
#pragma unroll
        for (int i = 0; i < BNV / 2; i++) {
            uint32_t hi, lo;
            split2(fb[2*i], fb[2*i+1], hi, lo);
            *(uint32_t*)&Bkh[bkr][bn0 + 2*i] = hi;
            *(uint32_t*)&Bkl[bkr][bn0 + 2*i] = lo;
        }
        __syncthreads();
        if (c + 1 < nch) {
            const float* ap = Ap + (c + 1) * 32;
#pragma unroll
            for (int i = 0; i < 2; i++) {
                float4 v = *(const float4*)(ap + i * 4);
                fa[i*4+0] = v.x; fa[i*4+1] = v.y; fa[i*4+2] = v.z; fa[i*4+3] = v.w;
            }
            const float* bp = Bp + (long)(c + 1) * 32 * ldb;
#pragma unroll
            for (int i = 0; i < BNV / 4; i++) {
                float4 v = *(const float4*)(bp + i * 4);
                fb[i*4+0] = v.x; fb[i*4+1] = v.y; fb[i*4+2] = v.z; fb[i*4+3] = v.w;
            }
        }
#pragma unroll
        for (int s = 0; s < 2; s++) {
            const int k16 = s * 16;
            uint32_t bhf[NJ][2], blf[NJ][2];
#pragma unroll
            for (int njp = 0; njp < NJ / 2; njp++) {
                int n = wn + njp * 16 + b_nc;
                ldsm4t(bhf[njp*2][0], bhf[njp*2][1], bhf[njp*2+1][0], bhf[njp*2+1][1],
                       &Bkh[k16 + b_kr][n]);
                ldsm4t(blf[njp*2][0], blf[njp*2][1], blf[njp*2+1][0], blf[njp*2+1][1],
                       &Bkl[k16 + b_kr][n]);
            }
#pragma unroll
            for (int mi = 0; mi < 2; mi++) {
                int r = wm + mi * 16 + a_r;
                uint32_t ah[4], al[4];
                ldsm4(ah[0], ah[1], ah[2], ah[3], &Ah[r][k16 + a_c]);
                ldsm4(al[0], al[1], al[2], al[3], &Al[r][k16 + a_c]);
#pragma unroll
                for (int nj = 0; nj < NJ; nj++) {
                    mma16816(acc[mi][nj], ah, bhf[nj]);
                    mma16816(acc[mi][nj], ah, blf[nj]);
                    mma16816(acc[mi][nj], al, bhf[nj]);
                }
            }
        }
        __syncthreads();
    }

#pragma unroll
    for (int mi = 0; mi < 2; mi++) {
        int row = rowBase + wm + mi * 16 + gr;
#pragma unroll
        for (int nj = 0; nj < NJ; nj++) {
            int col = colBase + wn + nj * 8 + (lane & 3) * 2;
            float a0 = acc[mi][nj][0], a1 = acc[mi][nj][1];
            float a2 = acc[mi][nj][2], a3 = acc[mi][nj][3];
            float v0 = alpha * a0 + ((row == col)     ? addDiag : 0.f);
            float v1 = alpha * a1 + ((row == col + 1) ? addDiag : 0.f);
            float v2 = alpha * a2 + ((row + 8 == col)     ? addDiag : 0.f);
            float v3 = alpha * a3 + ((row + 8 == col + 1) ? addDiag : 0.f);
            *(float2*)(C + (long)row * ldc + col)       = make_float2(v0, v1);
            *(float2*)(C + (long)(row + 8) * ldc + col) = make_float2(v2, v3);
            if (C2) {
                float w0 = alpha2 * a0 + ((row == col)     ? diag2 : 0.f);
                float w1 = alpha2 * a1 + ((row == col + 1) ? diag2 : 0.f);
                float w2 = alpha2 * a2 + ((row + 8 == col)     ? diag2 : 0.f);
                float w3 = alpha2 * a3 + ((row + 8 == col + 1) ? diag2 : 0.f);
                *(float2*)(C2 + (long)row * ldc + col)       = make_float2(w0, w1);
                *(float2*)(C2 + (long)(row + 8) * ldc + col) = make_float2(w2, w3);
            }
        }
    }
}

template<int BN>
static void TG3(const float* A, const float* B, float* C, float* C2,
                int M, int N, int K, int lda, int ldb, int ldc,
                long sA1, long sB1, long sC, int nz,
                float alpha, float addDiag, float alpha2, float diag2, cudaStream_t st)
{
    dim3 g(N / BN, M >> 6, nz);
    tg3<BN><<<g, 256, 0, st>>>(A, B, C, C2, K, lda, ldb, ldc, sA1, sB1, sC,
                               alpha, addDiag, alpha2, diag2);
}

// ============ flash attn3 (unchanged from R12) ============
#define F3_SMEM (8*9216 + 2048)
__global__ void __launch_bounds__(256)
flash3(const float* __restrict__ QKV, const float* __restrict__ QL,
       float* __restrict__ AVP, float* __restrict__ MM, float* __restrict__ SS)
{
    extern __shared__ char sm_[];
    __nv_bfloat16 (*Qh)[72] = (__nv_bfloat16(*)[72])(sm_);
    __nv_bfloat16 (*Qlw)[72] = (__nv_bfloat16(*)[72])(sm_ + 9216);
    __nv_bfloat16 (*Kh)[72] = (__nv_bfloat16(*)[72])(sm_ + 18432);
    __nv_bfloat16 (*Kl)[72] = (__nv_bfloat16(*)[72])(sm_ + 27648);
    __nv_bfloat16 (*Vh)[72] = (__nv_bfloat16(*)[72])(sm_ + 36864);
    __nv_bfloat16 (*Vl)[72] = (__nv_bfloat16(*)[72])(sm_ + 46080);
    __nv_bfloat16 (*Ph)[72] = (__nv_bfloat16(*)[72])(sm_ + 55296);
    __nv_bfloat16 (*Pl)[72] = (__nv_bfloat16(*)[72])(sm_ + 64512);
    float* red = (float*)(sm_ + 73728);
    const int tid = threadIdx.x, warp = tid >> 5, lane = tid & 31;
    const int l2 = lane & 3, gr = lane >> 2;
    const int ns = blockIdx.x, rb = blockIdx.y, z = blockIdx.z;
    const int b = z >> 3, h = z & 7;
    const int wm = (warp & 1) << 5, cg = warp >> 1, wn = cg << 4;
    const int a_r = (lane & 7) + ((lane >> 3) & 1) * 8, a_c = (lane >> 4) << 3;
    const int b_r = lane & 7, b_nj = (lane >> 4) & 1, b_c = ((lane >> 3) & 1) << 3;
    const int b_kr = (lane & 7) + ((lane >> 3) & 1) * 8, b_nc = (lane >> 4) << 3;
    const int lr = tid >> 2, lh = (tid & 3) << 4;

    {
        const float* qp = QL + (long)z * LM * DH + (long)(rb * 64 + lr) * DH + lh;
#pragma unroll
        for (int i = 0; i < 4; i++) {
            float4 v = *(const float4*)(qp + i * 4);
            uint32_t hi, lo;
            split2(v.x, v.y, hi, lo);
            *(uint32_t*)&Qh[lr][lh + i*4]     = hi; *(uint32_t*)&Qlw[lr][lh + i*4]     = lo;
            split2(v.z, v.w, hi, lo);
            *(uint32_t*)&Qh[lr][lh + i*4 + 2] = hi; *(uint32_t*)&Qlw[lr][lh + i*4 + 2] = lo;
        }
    }
    float accav[2][2][4];
    float mrun[2][2], srun[2][2];
#pragma unroll
    for (int i = 0; i < 2; i++)
#pragma unroll
        for (int t = 0; t < 2; t++) { mrun[i][t] = -3.0e38f; srun[i][t] = 0.f; }
#pragma unroll
    for (int i = 0; i < 2; i++)
#pragma unroll
        for (int j = 0; j < 2; j++)
#pragma unroll
            for (int t = 0; t < 4; t++) accav[i][j][t] = 0.f;

    const float* kvb = QKV + (long)b * NPD * D3 + h * DH;
    for (int c = 0; c < 26; c++) {
        long tb = (long)ns * KCH + c * 64;
        {
            const float* kp = kvb + (tb + lr) * D3 + DD + lh;
            const float* vp = kvb + (tb + lr) * D3 + 2 * DD + lh;
#pragma unroll
            for (int i = 0; i < 4; i++) {
                float4 v = *(const float4*)(kp + i * 4);
                uint32_t hi, lo;
                split2(v.x, v.y, hi, lo);
                *(uint32_t*)&Kh[lr][lh + i*4]     = hi; *(uint32_t*)&Kl[lr][lh + i*4]     = lo;
                split2(v.z, v.w, hi, lo);
                *(uint32_t*)&Kh[lr][lh + i*4 + 2] = hi; *(uint32_t*)&Kl[lr][lh + i*4 + 2] = lo;
                float4 w = *(const float4*)(vp + i * 4);
                split2(w.x, w.y, hi, lo);
                *(uint32_t*)&Vh[lr][lh + i*4]     = hi; *(uint32_t*)&Vl[lr][lh + i*4]     = lo;
                split2(w.z, w.w, hi, lo);
                *(uint32_t*)&Vh[lr][lh + i*4 + 2] = hi; *(uint32_t*)&Vl[lr][lh + i*4 + 2] = lo;
            }
        }
        __syncthreads();
        float acc[2][2][4];
#pragma unroll
        for (int i = 0; i < 2; i++)
#pragma unroll
            for (int j = 0; j < 2; j++)
#pragma unroll
                for (int t = 0; t < 4; t++) acc[i][j][t] = 0.f;
#pragma unroll
        for (int s = 0; s < 4; s++) {
            const int k16 = s * 16;
            uint32_t bhf[2][2], blf[2][2];
            {
                int n = wn + b_nj * 8 + b_r;
                ldsm4(bhf[0][0], bhf[0][1], bhf[1][0], bhf[1][1], &Kh[n][k16 + b_c]);
                ldsm4(blf[0][0], blf[0][1], blf[1][0], blf[1][1], &Kl[n][k16 + b_c]);
            }
#pragma unroll
            for (int mi = 0; mi < 2; mi++) {
                int r = wm + mi * 16 + a_r;
                uint32_t ah[4], al[4];
                ldsm4(ah[0], ah[1], ah[2], ah[3], &Qh[r][k16 + a_c]);
                ldsm4(al[0], al[1], al[2], al[3], &Qlw[r][k16 + a_c]);
#pragma unroll
                for (int nj = 0; nj < 2; nj++) {
                    mma16816(acc[mi][nj], ah, bhf[nj]);
                    mma16816(acc[mi][nj], ah, blf[nj]);
                    mma16816(acc[mi][nj], al, bhf[nj]);
                }
            }
        }
#pragma unroll
        for (int mi = 0; mi < 2; mi++)
#pragma unroll
            for (int nj = 0; nj < 2; nj++)
#pragma unroll
                for (int t = 0; t < 4; t++) acc[mi][nj][t] *= QSCALE;
#pragma unroll
        for (int mi = 0; mi < 2; mi++)
#pragma unroll
            for (int t = 0; t < 2; t++) {
                float m = fmaxf(fmaxf(acc[mi][0][2*t], acc[mi][0][2*t+1]),
                                fmaxf(acc[mi][1][2*t], acc[mi][1][2*t+1]));
                m = fmaxf(m, __shfl_xor_sync(0xffffffffu, m, 1));
                m = fmaxf(m, __shfl_xor_sync(0xffffffffu, m, 2));
                red[(wm + mi * 16 + gr + t * 8) * 4 + cg] = m;
            }
        __syncthreads();
#pragma unroll
        for (int mi = 0; mi < 2; mi++)
#pragma unroll
            for (int t = 0; t < 2; t++) {
                const float* r4 = red + (wm + mi * 16 + gr + t * 8) * 4;
                float mc = fmaxf(fmaxf(r4[0], r4[1]), fmaxf(r4[2], r4[3]));
                float mnew = fmaxf(mrun[mi][t], mc);
                float f = __expf(mrun[mi][t] - mnew);
                mrun[mi][t] = mnew;
                float sc = 0.f;
#pragma unroll
                for (int nj = 0; nj < 2; nj++) {
                    float e0 = __expf(acc[mi][nj][2*t]   - mnew);
                    float e1 = __expf(acc[mi][nj][2*t+1] - mnew);
                    acc[mi][nj][2*t] = e0; acc[mi][nj][2*t+1] = e1;
                    sc += e0 + e1;
                    accav[mi][nj][2*t] *= f; accav[mi][nj][2*t+1] *= f;
                }
                sc += __shfl_xor_sync(0xffffffffu, sc, 1);
                sc += __shfl_xor_sync(0xffffffffu, sc, 2);
                srun[mi][t] = srun[mi][t] * f + sc;
                int row = wm + mi * 16 + gr + t * 8;
#pragma unroll
                for (int nj = 0; nj < 2; nj++) {
                    int col = wn + nj * 8 + l2 * 2;
                    uint32_t hi, lo;
                    split2(acc[mi][nj][2*t], acc[mi][nj][2*t+1], hi, lo);
                    *(uint32_t*)&Ph[row][col] = hi;
                    *(uint32_t*)&Pl[row][col] = lo;
                }
            }
        __syncthreads();
#pragma unroll
        for (int s = 0; s < 4; s++) {
            const int k16 = s * 16;
            uint32_t bhf[2][2], blf[2][2];
            ldsm4t(bhf[0][0], bhf[0][1], bhf[1][0], bhf[1][1], &Vh[k16 + b_kr][wn + b_nc]);
            ldsm4t(blf[0][0], blf[0][1], blf[1][0], blf[1][1], &Vl[k16 + b_kr][wn + b_nc]);
#pragma unroll
            for (int mi = 0; mi < 2; mi++) {
                int r = wm + mi * 16 + a_r;
                uint32_t ah[4], al[4];
                ldsm4(ah[0], ah[1], ah[2], ah[3], &Ph[r][k16 + a_c]);
                ldsm4(al[0], al[1], al[2], al[3], &Pl[r][k16 + a_c]);
#pragma unroll
                for (int nj = 0; nj < 2; nj++) {
                    mma16816(accav[mi][nj], ah, bhf[nj]);
                    mma16816(accav[mi][nj], ah, blf[nj]);
                    mma16816(accav[mi][nj], al, bhf[nj]);
                }
            }
        }
        __syncthreads();
    }

#pragma unroll
    for (int mi = 0; mi < 2; mi++)
#pragma unroll
        for (int t = 0; t < 2; t++) {
            if (l2 == 0) red[(wm + mi * 16 + gr + t * 8) * 4 + cg] = srun[mi][t];
        }
    __syncthreads();
    float* avp = AVP + (((long)z * NSPL + ns) * LM + rb * 64) * DH;
#pragma unroll
    for (int mi = 0; mi < 2; mi++)
#pragma unroll
        for (int t = 0; t < 2; t++) {
            int row = wm + mi * 16 + gr + t * 8;
#pragma unroll
            for (int nj = 0; nj < 2; nj++) {
                int col = wn + nj * 8 + l2 * 2;
                *(float2*)(avp + (long)row * DH + col) =
                    make_float2(accav[mi][nj][2*t], accav[mi][nj][2*t+1]);
            }
            if (cg == 0 && l2 == 0) {
                const float* r4 = red + row * 4;
                long mi_idx = ((long)z * NSPL + ns) * LM + rb * 64 + row;
                MM[mi_idx] = mrun[mi][t];
                SS[mi_idx] = r4[0] + r4[1] + r4[2] + r4[3];
            }
        }
}

__global__ void f3comb(const float* __restrict__ AVP, const float* __restrict__ MM,
                       const float* __restrict__ SS, float* __restrict__ AV)
{
    int idx = blockIdx.x * 256 + threadIdx.x;
    int z = idx >> 14, r = (idx >> 6) & 255, d = idx & 63;
    long mbase = (long)z * NSPL * LM + r;
    float m = -3.0e38f;
#pragma unroll
    for (int ns = 0; ns < NSPL; ns++) m = fmaxf(m, __ldg(MM + mbase + (long)ns * LM));
    float s = 0.f, a = 0.f;
#pragma unroll
    for (int ns = 0; ns < NSPL; ns++) {
        float e = __expf(__ldg(MM + mbase + (long)ns * LM) - m);
        s += __ldg(SS + mbase + (long)ns * LM) * e;
        a += __ldg(AVP + ((long)(z * NSPL + ns) * LM + r) * DH + d) * e;
    }
    AV[idx] = a / s;
}

// ============ fused attn1 + softmax + @ZAV + V-conv residual -> AOUT ============
#define A1OH_SMEM 76800
__global__ void __launch_bounds__(256)
attn1oh(const float* __restrict__ QKV, const float* __restrict__ KL,
        const float* __restrict__ ZAV, const float* __restrict__ resk,
        float* __restrict__ aout)
{
    extern __shared__ char sm_[];
    const int tid = threadIdx.x, warp = tid >> 5, lane = tid & 31;
    const int l2 = lane & 3, gr = lane >> 2;
    int z = blockIdx.y, b = z >> 3, h = z & 7;
    const int rowBase = blockIdx.x << 6;
    const float* Qp = QKV + (long)b * NPD * D3 + h * DH;
    KL += (long)z * LM * DH;
    ZAV += (long)z * LM * DH;
    const int a_r = (lane & 7) + ((lane >> 3) & 1) * 8, a_c = (lane >> 4) << 3;
    const int b_r = lane & 7, b_nj = (lane >> 4) & 1, b_c = ((lane >> 3) & 1) << 3;

    const int rg = warp & 1, cg = warp >> 1;
    const int wm1 = rg << 5, wn1 = cg << 6;
    __nv_bfloat16 (*Ah)[40] = (__nv_bfloat16(*)[40])(sm_);
    __nv_bfloat16 (*Al)[40] = (__nv_bfloat16(*)[40])(sm_ + 5120);
    __nv_bfloat16 (*Bh)[40] = (__nv_bfloat16(*)[40])(sm_ + 10240);
    __nv_bfloat16 (*Bl)[40] = (__nv_bfloat16(*)[40])(sm_ + 30720);

    float acc[2][8][4];
#pragma unroll
    for (int i = 0; i < 2; i++)
#pragma unroll
        for (int j = 0; j < 8; j++)
#pragma unroll
            for (int t = 0; t < 4; t++) acc[i][j][t] = 0.f;

    const int lr = tid >> 2, lh = (tid & 3) << 3;
    for (int c = 0; c < 2; c++) {
        const float* ap = Qp + (long)(rowBase + lr) * D3 + c * 32 + lh;
#pragma unroll
        for (int i = 0; i < 2; i++) {
            float4 v = *(const float4*)(ap + i * 4);
            uint32_t hi, lo;
            split2(v.x, v.y, hi, lo);
            *(uint32_t*)&Ah[lr][lh + i*4]     = hi; *(uint32_t*)&Al[lr][lh + i*4]     = lo;
            split2(v.z, v.w, hi, lo);
            *(uint32_t*)&Ah[lr][lh + i*4 + 2] = hi; *(uint32_t*)&Al[lr][lh + i*4 + 2] = lo;
        }
        const float* bp = KL + (long)tid * DH + c * 32;
#pragma unroll
        for (int i = 0; i < 8; i++) {
            float4 v = *(const float4*)(bp + i * 4);
            uint32_t hi, lo;
            split2(v.x, v.y, hi, lo);
            *(uint32_t*)&Bh[tid][i*4]     = hi; *(uint32_t*)&Bl[tid][i*4]     = lo;
            split2(v.z, v.w, hi, lo);
            *(uint32_t*)&Bh[tid][i*4 + 2] = hi; *(uint32_t*)&Bl[tid][i*4 + 2] = lo;
        }
        __syncthreads();
#pragma unroll
        for (int s = 0; s < 2; s++) {
            const int k16 = s * 16;
            uint32_t bhf[8][2], blf[8][2];
#pragma unroll
            for (int njp = 0; njp < 4; njp++) {
                int n = wn1 + (njp * 2 + b_nj) * 8 + b_r;
                ldsm4(bhf[njp*2][0], bhf[njp*2][1], bhf[njp*2+1][0], bhf[njp*2+1][1],
                      &Bh[n][k16 + b_c]);
                ldsm4(blf[njp*2][0], blf[njp*2][1], blf[njp*2+1][0], blf[njp*2+1][1],
                      &Bl[n][k16 + b_c]);
            }
#pragma unroll
            for (int mi = 0; mi < 2; mi++) {
                int r = wm1 + mi * 16 + a_r;
                uint32_t ah[4], al[4];
                ldsm4(ah[0], ah[1], ah[2], ah[3], &Ah[r][k16 + a_c]);
                ldsm4(al[0], al[1], al[2], al[3], &Al[r][k16 + a_c]);
#pragma unroll
                for (int nj = 0; nj < 8; nj++) {
                    mma16816(acc[mi][nj], ah, bhf[nj]);
                    mma16816(acc[mi][nj], ah, blf[nj]);
                    mma16816(acc[mi][nj], al, bhf[nj]);
                }
            }
        }
        __syncthreads();
    }

#pragma unroll
    for (int i = 0; i < 2; i++)
#pragma unroll
        for (int j = 0; j < 8; j++)
#pragma unroll
            for (int t = 0; t < 4; t++) acc[i][j][t] *= QSCALE;

    float* red = (float*)sm_;
    float gmax[2][2], ginv[2][2];
#pragma unroll
    for (int mi = 0; mi < 2; mi++)
#pragma unroll
        for (int t = 0; t < 2; t++) {
            float m = -3.0e38f;
#pragma unroll
            for (int nj = 0; nj < 8; nj++)
                m = fmaxf(m, fmaxf(acc[mi][nj][2*t], acc[mi][nj][2*t+1]));
            m = fmaxf(m, __shfl_xor_sync(0xffffffffu, m, 1));
            m = fmaxf(m, __shfl_xor_sync(0xffffffffu, m, 2));
            red[(wm1 + mi * 16 + gr + t * 8) * 4 + cg] = m;
        }
    __syncthreads();
#pragma unroll
    for (int mi = 0; mi < 2; mi++)
#pragma unroll
        for (int t = 0; t < 2; t++) {
            const float* r4 = red + (wm1 + mi * 16 + gr + t * 8) * 4;
            gmax[mi][t] = fmaxf(fmaxf(r4[0], r4[1]), fmaxf(r4[2], r4[3]));
        }
    __syncthreads();
    float* red2 = red + 64 * 4;
#pragma unroll
    for (int mi = 0; mi < 2; mi++)
#pragma unroll
        for (int t = 0; t < 2; t++) {
            float s = 0.f;
#pragma unroll
            for (int nj = 0; nj < 8; nj++) {
                float e0 = __expf(acc[mi][nj][2*t]   - gmax[mi][t]);
                float e1 = __expf(acc[mi][nj][2*t+1] - gmax[mi][t]);
                acc[mi][nj][2*t] = e0; acc[mi][nj][2*t+1] = e1;
                s += e0 + e1;
            }
            s += __shfl_xor_sync(0xffffffffu, s, 1);
            s += __shfl_xor_sync(0xffffffffu, s, 2);
            red2[(wm1 + mi * 16 + gr + t * 8) * 4 + cg] = s;
        }
    __syncthreads();
#pragma unroll
    for (int mi = 0; mi < 2; mi++)
#pragma unroll
        for (int t = 0; t < 2; t++) {
            const float* r4 = red2 + (wm1 + mi * 16 + gr + t * 8) * 4;
            ginv[mi][t] = 1.f / (r4[0] + r4[1] + r4[2] + r4[3]);
        }
    __syncthreads();

    __nv_bfloat16 (*Ph)[264] = (__nv_bfloat16(*)[264])(sm_);
    __nv_bfloat16 (*Pl)[264] = (__nv_bfloat16(*)[264])(sm_ + 33792);
#pragma unroll
    for (int mi = 0; mi < 2; mi++)
#pragma unroll
        for (int t = 0; t < 2; t++) {
            int row = wm1 + mi * 16 + gr + t * 8;
#pragma unroll
            for (int nj = 0; nj < 8; nj++) {
                int col = wn1 + nj * 8 + l2 * 2;
                uint32_t hi, lo;
                split2(acc[mi][nj][2*t] * ginv[mi][t], acc[mi][nj][2*t+1] * ginv[mi][t], hi, lo);
                *(uint32_t*)&Ph[row][col] = hi;
                *(uint32_t*)&Pl[row][col] = lo;
            }
        }
    __syncthreads();

    const int wm3 = (warp & 1) << 5, wn3 = (warp >> 1) << 4;
    __nv_bfloat16 (*Bzh)[72] = (__nv_bfloat16(*)[72])(sm_ + 67584);
    __nv_bfloat16 (*Bzl)[72] = (__nv_bfloat16(*)[72])(sm_ + 67584 + 4608);
    const int zr = tid >> 3, zc = (tid & 7) << 3;
    float oacc[2][2][4];
#pragma unroll
    for (int i = 0; i < 2; i++)
#pragma unroll
        for (int j = 0; j < 2; j++)
#pragma unroll
            for (int t = 0; t < 4; t++) oacc[i][j][t] = 0.f;

    for (int kc = 0; kc < 8; kc++) {
        const float* zp = ZAV + (long)(kc * 32 + zr) * DH + zc;
#pragma unroll
        for (int i = 0; i < 2; i++) {
            float4 v = *(const float4*)(zp + i * 4);
            uint32_t hi, lo;
            split2(v.x, v.y, hi, lo);
            *(uint32_t*)&Bzh[zr][zc + i*4]     = hi; *(uint32_t*)&Bzl[zr][zc + i*4]     = lo;
            split2(v.z, v.w, hi, lo);
            *(uint32_t*)&Bzh[zr][zc + i*4 + 2] = hi; *(uint32_t*)&Bzl[zr][zc + i*4 + 2] = lo;
        }
        __syncthreads();
#pragma unroll
        for (int s = 0; s < 2; s++) {
            const int k16l = s * 16, k16g = kc * 32 + s * 16;
            uint32_t bhf[2][2], blf[2][2];
            ldsm4t(bhf[0][0], bhf[0][1], bhf[1][0], bhf[1][1],
                   &Bzh[k16l + (lane & 7) + ((lane >> 3) & 1) * 8][wn3 + ((lane >> 4) << 3)]);
            ldsm4t(blf[0][0], blf[0][1], blf[1][0], blf[1][1],
                   &Bzl[k16l + (lane & 7) + ((lane >> 3) & 1) * 8][wn3 + ((lane >> 4) << 3)]);
#pragma unroll
            for (int mi = 0; mi < 2; mi++) {
                int r = wm3 + mi * 16 + a_r;
                uint32_t ah[4], al[4];
                ldsm4(ah[0], ah[1], ah[2], ah[3], &Ph[r][k16g + a_c]);
                ldsm4(al[0], al[1], al[2], al[3], &Pl[r][k16g + a_c]);
#pragma unroll
                for (int nj = 0; nj < 2; nj++) {
                    mma16816(oacc[mi][nj], ah, bhf[nj]);
                    mma16816(oacc[mi][nj], ah, blf[nj]);
                    mma16816(oacc[mi][nj], al, bhf[nj]);
                }
            }
        }
        __syncthreads();
    }

    // ---------- epilogue: V-conv residual fused; write AOUT ----------
    float* Vt = (float*)sm_;                 // [96][65] overlays dead Ph region
    float* sw = (float*)(sm_ + 24960);       // 33 taps
    if (tid < 33) sw[tid] = resk[h * 33 + tid];
    const float* vb = QKV + (long)b * NPD * D3 + 2 * DD + h * DH;
    for (int i = tid; i < 96 * 64; i += 256) {
        int r = i >> 6, d = i & 63;
        long n = (long)rowBase + r - 16;
        Vt[r * 65 + d] = (n >= 0 && n < NPD) ? vb[n * D3 + d] : 0.f;
    }
    __syncthreads();
    float* ab = aout + (long)b * NPD * DD + h * DH;
#pragma unroll
    for (int mi = 0; mi < 2; mi++) {
        int rl = wm3 + mi * 16 + gr;
#pragma unroll
        for (int nj = 0; nj < 2; nj++) {
            int col = wn3 + nj * 8 + l2 * 2;
            float c00 = 0.f, c01 = 0.f, c10 = 0.f, c11 = 0.f;
#pragma unroll
            for (int j = 0; j < 33; j++) {
                float w = sw[j];
                c00 += w * Vt[(rl + j) * 65 + col];
                c01 += w * Vt[(rl + j) * 65 + col + 1];
                c10 += w * Vt[(rl + 8 + j) * 65 + col];
                c11 += w * Vt[(rl + 8 + j) * 65 + col + 1];
            }
            long n0 = rowBase + rl;
            *(float2*)(ab + n0 * DD + col) =
                make_float2(oacc[mi][nj][0] + c00, oacc[mi][nj][1] + c01);
            *(float2*)(ab + (n0 + 8) * DD + col) =
                make_float2(oacc[mi][nj][2] + c10, oacc[mi][nj][3] + c11);
        }
    }
}

// weight prep
__global__ void wprep(const float* __restrict__ W, __nv_bfloat16* __restrict__ out, int K, int N) {
    long idx = (long)blockIdx.x * 256 + threadIdx.x;
    if (idx >= (long)K * N) return;
    int n = (int)(idx / K), k = (int)(idx - (long)n * K);
    float v = __ldg(W + (long)k * N + n);
    __nv_bfloat16 h = __float2bfloat16(v);
    out[idx] = h;
    out[(long)N * K + idx] = __float2bfloat16(v - __bfloat162float(h));
}

// LN row stats: (mu, rstd) per token row of an NC-layout buffer
__global__ void lnstats(const float* __restrict__ H, float* __restrict__ mur) {
    __shared__ float shm[32];
    long t = blockIdx.x;                     // BB*NC rows
    const float* row = H + t * DD;
    int c0 = threadIdx.x * 4;
    float4 v = *(const float4*)(row + c0);
    float mu = brsum(v.x + v.y + v.z + v.w, shm) * (1.f / DD);
    float d0 = v.x-mu, d1 = v.y-mu, d2 = v.z-mu, d3 = v.w-mu;
    float var = brsum(d0*d0 + d1*d1 + d2*d2 + d3*d3, shm) * (1.f / DD);
    if (threadIdx.x == 0) { mur[t*2] = mu; mur[t*2+1] = rsqrtf(var + 1e-5f); }
}

template<int V>
__device__ __forceinline__ void ldv(float* r, const float* __restrict__ p) {
    if constexpr (V == 2) { float2 t = *(const float2*)p; r[0]=t.x; r[1]=t.y; }
    else if constexpr (V == 4) { float4 t = *(const float4*)p; r[0]=t.x; r[1]=t.y; r[2]=t.z; r[3]=t.w; }
    else if constexpr (V == 8) { ldv<4>(r, p); ldv<4>(r + 4, p + 4); }
}
__device__ __forceinline__ float brmax_(float v) { return v; }

// ---------------- fused GEMM + row softmax (attn2) ----------------
__global__ void __launch_bounds__(256)
attn_sm_kernel(const float* __restrict__ A, const float* __restrict__ B,
               float* __restrict__ C, int lda, long sAb, long sAh, long sCz)
{
    int z = blockIdx.y, b = z >> 3, h = z & 7;
    A += (long)b * sAb + (long)h * sAh;
    B += (long)z * (LM * DH);
    C += (long)z * sCz;
    __shared__ float As[2][8][64];
    __shared__ float Bs[2][8][256];
    const int tid = threadIdx.x, tx = tid & 15, ty = tid >> 4;
    const int rowBase = blockIdx.x * 64;
    const int arow = tid >> 2, acol = (tid & 3) * 2;
    const float* Ap = A + (long)(rowBase + arow) * lda + acol;
    const float* Bp = B + tid * DH;
    float ra[2], rb[8];
    float acc[4][16];
#pragma unroll
    for (int i = 0; i < 4; i++)
#pragma unroll
        for (int j = 0; j < 16; j++) acc[i][j] = 0.f;

    ldv<2>(ra, Ap);
    ldv<8>(rb, Bp);
    As[0][acol][arow] = ra[0]; As[0][acol + 1][arow] = ra[1];
#pragma unroll
    for (int i = 0; i < 8; i++) Bs[0][i][tid] = rb[i];
    __syncthreads();

    for (int kb = 0; kb < 8; kb++) {
        int cur = kb & 1;
        if (kb + 1 < 8) { ldv<2>(ra, Ap + (kb + 1) * 8); ldv<8>(rb, Bp + (kb + 1) * 8); }
#pragma unroll
        for (int k = 0; k < 8; k++) {
            float a[4], bv[16];
#pragma unroll
            for (int i = 0; i < 4; i++) a[i] = As[cur][k][ty * 4 + i];
#pragma unroll
            for (int j = 0; j < 16; j++) bv[j] = Bs[cur][k][tx * 16 + j];
#pragma unroll
            for (int i = 0; i < 4; i++)
#pragma unroll
                for (int j = 0; j < 16; j++) acc[i][j] += a[i] * bv[j];
        }
        if (kb + 1 < 8) {
            int nxt = cur ^ 1;
            As[nxt][acol][arow] = ra[0]; As[nxt][acol + 1][arow] = ra[1];
#pragma unroll
            for (int i = 0; i < 8; i++) Bs[nxt][i][tid] = rb[i];
        }
        __syncthreads();
    }

#pragma unroll
    for (int i = 0; i < 4; i++) {
        float m = -3.0e38f;
#pragma unroll
        for (int j = 0; j < 16; j++) { acc[i][j] *= QSCALE; m = fmaxf(m, acc[i][j]); }
#pragma unroll
        for (int o = 8; o; o >>= 1) m = fmaxf(m, __shfl_xor_sync(0xffffffffu, m, o));
        float s = 0.f;
#pragma unroll
        for (int j = 0; j < 16; j++) { float e = __expf(acc[i][j] - m); acc[i][j] = e; s += e; }
#pragma unroll
        for (int o = 8; o; o >>= 1) s += __shfl_xor_sync(0xffffffffu, s, o);
        float inv = 1.f / s;
        int row = rowBase + ty * 4 + i;
        float* crow = C + (long)row * LM + tx * 16;
#pragma unroll
        for (int j = 0; j < 16; j += 4) {
            float4 o = make_float4(acc[i][j] * inv, acc[i][j+1] * inv, acc[i][j+2] * inv, acc[i][j+3] * inv);
            *(float4*)(crow + j) = o;
        }
    }
}

// ---------------- small kernels ----------------
__global__ void cls_kernel(float* H, const float* cls) {
    int i = blockIdx.x * 256 + threadIdx.x;
    if (i >= BB * DD) return;
    int b = i / DD, c = i - b * DD;
    H[(long)b * NC * DD + c] = cls[c];
}
__global__ void h2cls_kernel(const float* __restrict__ H, float* __restrict__ H2) {
    int i = blockIdx.x * 256 + threadIdx.x;
    if (i >= BB * DD) return;
    int b = i / DD, c = i - b * DD;
    H2[(long)b * NC * DD + c] = H[(long)b * NC * DD + c];
}
__global__ void landmark_kernel(const float* __restrict__ qkv, float* __restrict__ ql,
                                float* __restrict__ kl) {
    int i = blockIdx.x, z = blockIdx.y, d = threadIdx.x;
    int b = z >> 3, h = z & 7;
    const float* base = qkv + (long)b * NPD * D3 + (long)i * LCH * D3 + h * DH + d;
    float sq = 0.f, sk = 0.f;
    for (int j = 0; j < LCH; j++) { sq += base[(long)j * D3]; sk += base[(long)j * D3 + DD]; }
    ql[((long)z * LM + i) * DH + d] = sq * (1.f / LCH);
    kl[((long)z * LM + i) * DH + d] = sk * (1.f / LCH);
}
__global__ void zero_sc_kernel(int* sc) { if (threadIdx.x < 2) sc[threadIdx.x] = 0; }
__global__ void pinv_norm_kernel(const float* __restrict__ a2, int* mr, int* mc) {
    int z = blockIdx.x, t = threadIdx.x;
    const float* A = a2 + (long)z * LM * LM;
    float rs = 0.f, cs = 0.f;
    for (int j = 0; j < LM; j++) { rs += A[t * LM + j]; cs += A[j * LM + t]; }
    atomicMax(mr, __float_as_int(rs));
    atomicMax(mc, __float_as_int(cs));
}
__global__ void pinv_init_kernel(const float* __restrict__ a2, float* __restrict__ z0,
                                 const int* __restrict__ sc) {
    float inv = 1.f / (__int_as_float(sc[0]) * __int_as_float(sc[1]));
    long idx = (long)blockIdx.x * 256 + threadIdx.x;
    long zz = idx >> 16;
    int i = (int)((idx >> 8) & 255), j = (int)(idx & 255);
    z0[idx] = a2[(zz << 16) + ((long)j << 8) + i] * inv;
}
__global__ void wt_kernel(const float* k7, const float* k5, const float* k3, float* wt) {
    int idx = blockIdx.x * 256 + threadIdx.x;
    if (idx >= 49 * DD) return;
    int o = idx / DD, c = idx - o * DD;
    int dy = o / 7, dx = o - dy * 7;
    float w = k7[c * 49 + o];
    if (dy >= 1 && dy <= 5 && dx >= 1 && dx <= 5) w += k5[c * 25 + (dy-1)*5 + (dx-1)];
    if (dy >= 2 && dy <= 4 && dx >= 2 && dx <= 4) w += k3[c * 9 + (dy-2)*3 + (dx-2)];
    if (dy == 3 && dx == 3) w += 1.f;
    wt[o * DD + c] = w;
}
#define PPEG_SMEM ((22*22*64 + 49*64) * 4)
__global__ void __launch_bounds__(256)
ppeg_tile_kernel(const float* __restrict__ H, const float* __restrict__ wt,
                 const float* __restrict__ b7, const float* __restrict__ b5,
                 const float* __restrict__ b3, float* __restrict__ H2) {
    extern __shared__ float ps[];
    float* sw = ps;
    float* sv = ps + 49 * 64;
    int tile = blockIdx.x;
    int ty0 = (tile >> 3) << 4, tx0 = (tile & 7) << 4;
    int cg = blockIdx.y << 6;
    int b = blockIdx.z;
    int tid = threadIdx.x;
    const float* img = H + ((long)b * NC + 1) * DD;
    for (int i = tid; i < 49 * 64; i += 256)
        sw[i] = wt[(i >> 6) * DD + cg + (i & 63)];
    for (int i = tid; i < 22 * 22 * 64; i += 256) {
        int c = i & 63, pix = i >> 6;
        int yy = pix / 22, xx = pix - yy * 22;
        int gy = ty0 - 3 + yy, gx = tx0 - 3 + xx;
        sv[i] = ((unsigned)gy < 128u && (unsigned)gx < 128u)
                ? img[((long)((gy << 7) + gx)) * DD + cg + c] : 0.f;
    }
    __syncthreads();
    int c = tid & 63, q = tid >> 6;
    float bsum = __ldg(b7 + cg + c) + __ldg(b5 + cg + c) + __ldg(b3 + cg + c);
    for (int p = 0; p < 64; p++) {
        int pix = p * 4 + q;
        int y = pix >> 4, x = pix & 15;
        float acc = bsum;
#pragma unroll
        for (int dy = 0; dy < 7; dy++)
#pragma unroll
            for (int dx = 0; dx < 7; dx++)
                acc += sw[(dy * 7 + dx) * 64 + c] * sv[(((y + dy) * 22) + x + dx) * 64 + c];
        H2[((long)b * NC + 1 + ((ty0 + y) << 7) + tx0 + x) * DD + cg + c] = acc;
    }
}
__global__ void final_kernel(const float* __restrict__ H, const float* __restrict__ g,
                             const float* __restrict__ be, const float* __restrict__ W2,
                             const float* __restrict__ b2, float* __restrict__ out) {
    __shared__ float shm[32];
    int b = blockIdx.x;
    const float* row = H + (long)b * NC * DD;
    int c0 = threadIdx.x * 4;
    float4 v = *(const float4*)(row + c0);
    float mu = brsum(v.x + v.y + v.z + v.w, shm) * (1.f / DD);
    float d0 = v.x-mu, d1 = v.y-mu, d2 = v.z-mu, d3 = v.w-mu;
    float var = brsum(d0*d0 + d1*d1 + d2*d2 + d3*d3, shm) * (1.f / DD);
    float r = rsqrtf(var + 1e-5f);
    float4 gg = *(const float4*)(g + c0), bb = *(const float4*)(be + c0);
    float4 w = *(const float4*)(W2 + c0);
    float o = (d0*r*gg.x+bb.x)*w.x + (d1*r*gg.y+bb.y)*w.y +
              (d2*r*gg.z+bb.z)*w.z + (d3*r*gg.w+bb.w)*w.w;
    o = brsum(o, shm);
    if (threadIdx.x == 0) out[b] = o + b2[0];
}

static void attention(float* hbuf, float* base,
                      const __nv_bfloat16* wqkv_bf, const __nv_bfloat16* wout_bf,
                      const float* bout, const float* resk, const float* g, const float* be,
                      cudaStream_t s2, cudaEvent_t evA, cudaEvent_t evB)
{
    float *MUR = base+OFF_MUR, *QKV = base+OFF_QKV, *AOUT = base+OFF_AOUT;
    float *QL = base+OFF_QL, *KL = base+OFF_KL, *A2 = base+OFF_A2;
    float *Z0 = base+OFF_Z0, *Z1 = base+OFF_Z1, *XZ = base+OFF_XZ;
    float *T1 = base+OFF_T1, *T2 = base+OFF_T2, *AV = base+OFF_AV, *ZAV = base+OFF_ZAV;
    float *AVP = base+OFF_AVP, *M3 = base+OFF_M3, *S3 = base+OFF_S3;
    int* SC = (int*)(base + OFF_SC);
    const long s = (long)LM * LM;
    const long LMDH = (long)LM * DH;

    // LN fused into QKV GEMM loader (stats only; pads are exact zeros in loader)
    lnstats<<<BB * NC, 128>>>(hbuf, MUR);
    TG<false,false,false,true>(hbuf, wqkv_bf, nullptr, QKV, NPD, D3, DD, DD, D3,
                               (long)NC*DD, (long)NPD*D3, BB, g, be, MUR);
    landmark_kernel<<<dim3(LM, BB*NH), 64>>>(QKV, QL, KL);
    attn_sm_kernel<<<dim3(LM/64, BB*NH), 256>>>(QL, KL, A2, DH, (long)NH*LM*DH, LMDH, (long)LM*LM);

    // ---- fork pinv chain onto side stream ----
    cudaEventRecord(evA, 0);
    cudaStreamWaitEvent(s2, evA, 0);
    zero_sc_kernel<<<1, 32, 0, s2>>>(SC);
    pinv_norm_kernel<<<16, 256, 0, s2>>>(A2, SC, SC + 1);
    pinv_init_kernel<<<4096, 256, 0, s2>>>(A2, Z0, SC);
    for (int it = 0; it < 6; it++) {
        float* Zin = (it & 1) ? Z1 : Z0;
        float* Zout = (it & 1) ? Z0 : Z1;
        TG3<128>(A2, Zin, XZ, T1, LM, LM, LM, LM, LM, LM, s, s, s, 16, 1.f, 0.f, -1.f, 7.f, s2);
        TG3<128>(XZ, T1, T2, nullptr, LM, LM, LM, LM, LM, LM, s, s, s, 16, -1.f, 15.f, 0.f, 0.f, s2);
        TG3<128>(XZ, T2, T1, nullptr, LM, LM, LM, LM, LM, LM, s, s, s, 16, -1.f, 13.f, 0.f, 0.f, s2);
        TG3<128>(Zin, T1, Zout, nullptr, LM, LM, LM, LM, LM, LM, s, s, s, 16, 0.25f, 0.f, 0.f, 0.f, s2);
    }
    cudaEventRecord(evB, s2);

    // ---- main stream: fused flash attn3 -> AV ----
    cudaFuncSetAttribute(flash3, cudaFuncAttributeMaxDynamicSharedMemorySize, F3_SMEM);
    flash3<<<dim3(NSPL, 4, 16), 256, F3_SMEM>>>(QKV, QL, AVP, M3, S3);
    f3comb<<<16*LM*DH/256, 256>>>(AVP, M3, S3, AV);

    // ---- join: pinv result needed ----
    cudaStreamWaitEvent(0, evB, 0);
    TG3<64>(Z0, AV, ZAV, nullptr, LM, DH, LM, LM, DH, DH,
            s, LMDH, LMDH, 16, 1.f, 0.f, 0.f, 0.f, 0);
    // fused attn1 + softmax + @ZAV + V-conv residual -> AOUT
    cudaFuncSetAttribute(attn1oh, cudaFuncAttributeMaxDynamicSharedMemorySize, A1OH_SMEM);
    attn1oh<<<dim3(NPD/64, BB*NH), 256, A1OH_SMEM>>>(QKV, KL, ZAV, resk, AOUT);
    TG<true,false,true,false>(AOUT, wout_bf, bout, hbuf, NPD, DD, DD, DD, DD,
                              (long)NPD*DD, (long)NC*DD, BB);
}

extern "C" void kernel_launch(void* const* d_in, const int* in_sizes, int n_in,
                              void* d_out, int out_size) {
    const float* features = (const float*)d_in[0];
    const float* W1    = (const float*)d_in[1];
    const float* b1    = (const float*)d_in[2];
    const float* cls   = (const float*)d_in[3];
    const float* ln1_g = (const float*)d_in[4];
    const float* ln1_b = (const float*)d_in[5];
    const float* Wqkv1 = (const float*)d_in[6];
    const float* Wout1 = (const float*)d_in[7];
    const float* bout1 = (const float*)d_in[8];
    const float* resk1 = (const float*)d_in[9];
    const float* ln2_g = (const float*)d_in[10];
    const float* ln2_b = (const float*)d_in[11];
    const float* Wqkv2 = (const float*)d_in[12];
    const float* Wout2 = (const float*)d_in[13];
    const float* bout2 = (const float*)d_in[14];
    const float* resk2 = (const float*)d_in[15];
    const float* k7    = (const float*)d_in[16];
    const float* b7c   = (const float*)d_in[17];
    const float* k5    = (const float*)d_in[18];
    const float* b5c   = (const float*)d_in[19];
    const float* k3    = (const float*)d_in[20];
    const float* b3c   = (const float*)d_in[21];
    const float* lnf_g = (const float*)d_in[22];
    const float* lnf_b = (const float*)d_in[23];
    const float* W2    = (const float*)d_in[24];
    const float* b2    = (const float*)d_in[25];

    float* base = nullptr;
    cudaGetSymbolAddress((void**)&base, g_buf);
    float* H = base + OFF_H;
    float* H2 = base + OFF_H2;
    __nv_bfloat16* wbf = (__nv_bfloat16*)(base + OFF_WBF);

    cudaStream_t s2;
    cudaStreamCreateWithFlags(&s2, cudaStreamNonBlocking);
    cudaEvent_t evA, evB;
    cudaEventCreateWithFlags(&evA, cudaEventDisableTiming);
    cudaEventCreateWithFlags(&evB, cudaEventDisableTiming);

    wprep<<<(int)((1536L*512 + 255) / 256), 256>>>(W1,    wbf + WB_T1,   IND, DD);
    wprep<<<(int)((512L*1536 + 255) / 256), 256>>>(Wqkv1, wbf + WB_QKV1, DD,  D3);
    wprep<<<(int)((512L*1536 + 255) / 256), 256>>>(Wqkv2, wbf + WB_QKV2, DD,  D3);
    wprep<<<(int)((512L*512  + 255) / 256), 256>>>(Wout1, wbf + WB_OUT1, DD,  DD);
    wprep<<<(int)((512L*512  + 255) / 256), 256>>>(Wout2, wbf + WB_OUT2, DD,  DD);

    cls_kernel<<<4, 256>>>(H, cls);
    TG<true,true,false,false>(features, wbf + WB_T1, b1, H + DD, NTOK, DD, IND, IND, DD,
                              (long)NTOK*IND, (long)NC*DD, BB);

    attention(H, base, wbf + WB_QKV1, wbf + WB_OUT1, bout1, resk1, ln1_g, ln1_b, s2, evA, evB);

    wt_kernel<<<98, 256>>>(k7, k5, k3, base + OFF_WT);
    cudaFuncSetAttribute(ppeg_tile_kernel, cudaFuncAttributeMaxDynamicSharedMemorySize, PPEG_SMEM);
    ppeg_tile_kernel<<<dim3(64, 8, BB), 256, PPEG_SMEM>>>(H, base + OFF_WT, b7c, b5c, b3c, H2);
    h2cls_kernel<<<4, 256>>>(H, H2);

    attention(H2, base, wbf + WB_QKV2, wbf + WB_OUT2, bout2, resk2, ln2_g, ln2_b, s2, evA, evB);

    final_kernel<<<BB, 128>>>(H2, lnf_g, lnf_b, W2, b2, (float*)d_out);
}

// round 15
// speedup vs baseline: 1.1421x; 1.1421x over previous
#include <cuda_runtime.h>
#include <cuda_bf16.h>
#include <math.h>
#include <stdint.h>

#define BB 2
#define NTOK 16384
#define IND 1536
#define DD 512
#define NH 8
#define DH 64
#define LM 256
#define LCH 65
#define NPD 16640
#define NC 16385
#define PADN 255
#define D3 1536
#define QSCALE 0.125f
#define NSPL 10
#define KCH 1664    // NPD / NSPL

constexpr long SZ_H   = (long)BB*NC*DD;
constexpr long SZ_XLN = (long)BB*NPD*DD;
constexpr long SZ_QKV = (long)BB*NPD*D3;
constexpr long SZ_OH  = (long)BB*NH*NPD*DH;
constexpr long SZ_MM  = 16L*LM*LM;
constexpr long SZ_SV  = 16L*LM*DH;

constexpr long OFF_H    = 0;
constexpr long OFF_XLN  = OFF_H    + SZ_H;
constexpr long OFF_QKV  = OFF_XLN  + SZ_XLN;
constexpr long OFF_OH   = OFF_QKV  + SZ_QKV;
constexpr long OFF_AOUT = OFF_OH   + SZ_OH;
constexpr long OFF_H2   = OFF_AOUT + SZ_XLN;
constexpr long OFF_QL   = OFF_H2   + SZ_XLN;
constexpr long OFF_KL   = OFF_QL   + SZ_SV;
constexpr long OFF_A2   = OFF_KL   + SZ_SV;
constexpr long OFF_Z0   = OFF_A2   + SZ_MM;
constexpr long OFF_Z1   = OFF_Z0   + SZ_MM;
constexpr long OFF_XZ   = OFF_Z1   + SZ_MM;
constexpr long OFF_T1   = OFF_XZ   + SZ_MM;
constexpr long OFF_T2   = OFF_T1   + SZ_MM;
constexpr long OFF_AV   = OFF_T2   + SZ_MM;
constexpr long OFF_ZAV  = OFF_AV   + SZ_SV;
constexpr long OFF_WT   = OFF_ZAV  + SZ_SV;
constexpr long OFF_AVP  = OFF_WT   + 49L*DD;
constexpr long OFF_SC   = OFF_AVP  + 16L*NSPL*LM*DH;
constexpr long OFF_M3   = OFF_SC   + 16;          // [16][NSPL][256] row maxes
constexpr long OFF_S3   = OFF_M3   + 16L*NSPL*LM; // [16][NSPL][256] row sums
constexpr long OFF_WBF  = OFF_S3   + 16L*NSPL*LM;
constexpr long WBF_FLOATS = 2900000;
constexpr long TOTAL_F  = OFF_WBF + WBF_FLOATS;

__device__ __align__(256) float g_buf[TOTAL_F];

constexpr long WB_T1   = 0;
constexpr long WB_QKV1 = WB_T1   + 2L*512*1536;
constexpr long WB_QKV2 = WB_QKV1 + 2L*512*1536;
constexpr long WB_OUT1 = WB_QKV2 + 2L*512*1536;
constexpr long WB_OUT2 = WB_OUT1 + 2L*512*512;

// ---------------- mma.sync m16n8k16 bf16 + ldmatrix ----------------
__device__ __forceinline__ void mma16816(float* c, const uint32_t* a, const uint32_t* b) {
    asm volatile(
        "mma.sync.aligned.m16n8k16.row.col.f32.bf16.bf16.f32 "
        "{%0,%1,%2,%3}, {%4,%5,%6,%7}, {%8,%9}, {%0,%1,%2,%3};"
        : "+f"(c[0]), "+f"(c[1]), "+f"(c[2]), "+f"(c[3])
        : "r"(a[0]), "r"(a[1]), "r"(a[2]), "r"(a[3]), "r"(b[0]), "r"(b[1]));
}
__device__ __forceinline__ void ldsm4(uint32_t& r0, uint32_t& r1, uint32_t& r2, uint32_t& r3,
                                      const void* p) {
    uint32_t a = (uint32_t)__cvta_generic_to_shared(p);
    asm volatile("ldmatrix.sync.aligned.m8n8.x4.shared.b16 {%0,%1,%2,%3}, [%4];"
        : "=r"(r0), "=r"(r1), "=r"(r2), "=r"(r3) : "r"(a));
}
__device__ __forceinline__ void ldsm4t(uint32_t& r0, uint32_t& r1, uint32_t& r2, uint32_t& r3,
                                       const void* p) {
    uint32_t a = (uint32_t)__cvta_generic_to_shared(p);
    asm volatile("ldmatrix.sync.aligned.m8n8.x4.trans.shared.b16 {%0,%1,%2,%3}, [%4];"
        : "=r"(r0), "=r"(r1), "=r"(r2), "=r"(r3) : "r"(a));
}
__device__ __forceinline__ void split2(float x0, float x1, uint32_t& hi, uint32_t& lo) {
    __nv_bfloat16 h0 = __float2bfloat16(x0), h1 = __float2bfloat16(x1);
    __nv_bfloat16 l0 = __float2bfloat16(x0 - __bfloat162float(h0));
    __nv_bfloat16 l1 = __float2bfloat16(x1 - __bfloat162float(h1));
    __nv_bfloat162 hh = __halves2bfloat162(h0, h1);
    __nv_bfloat162 ll = __halves2bfloat162(l0, l1);
    hi = *(uint32_t*)&hh; lo = *(uint32_t*)&ll;
}

// ============ weight GEMM: C = A[M,K] @ W[K,N]; RESID: C=H, rows>=PADN accumulate ============
template<bool BIASF, bool RELUF, bool RESID>
__global__ void __launch_bounds__(256)
tgemm(const float* __restrict__ A, const __nv_bfloat16* __restrict__ Wh,
      const __nv_bfloat16* __restrict__ Wl, const float* __restrict__ bias,
      float* __restrict__ C, int K, int lda, int ldc, long sAb, long sCb)
{
    __shared__ __nv_bfloat16 Ah[128][40], Al[128][40], Bh[128][40], Bl[128][40];
    const int tid = threadIdx.x, warp = tid >> 5, lane = tid & 31;
    const int rowBase = blockIdx.y << 7, colBase = blockIdx.x << 7;
    A += (long)blockIdx.z * sAb;
    C += (long)blockIdx.z * sCb;
    const int lr = tid >> 1, lh = (tid & 1) << 4;
    const float* Ap = A + (long)(rowBase + lr) * lda + lh;
    const __nv_bfloat16* Bhp = Wh + (long)(colBase + lr) * K + lh;
    const __nv_bfloat16* Blp = Wl + (long)(colBase + lr) * K + lh;
    const int wm = (warp & 1) << 6, wn = (warp >> 1) << 5;
    const int gr = lane >> 2;
    const int a_r = (lane & 7) + ((lane >> 3) & 1) * 8;
    const int a_c = (lane >> 4) << 3;
    const int b_r = lane & 7;
    const int b_nj = (lane >> 4) & 1;
    const int b_c = ((lane >> 3) & 1) << 3;

    float acc[4][4][4];
#pragma unroll
    for (int i = 0; i < 4; i++)
#pragma unroll
        for (int j = 0; j < 4; j++)
#pragma unroll
            for (int t = 0; t < 4; t++) acc[i][j][t] = 0.f;

    float fa[16];
    uint4 vbh0, vbh1, vbl0, vbl1;
#pragma unroll
    for (int i = 0; i < 4; i++) {
        float4 v = *(const float4*)(Ap + i * 4);
        fa[i*4+0] = v.x; fa[i*4+1] = v.y; fa[i*4+2] = v.z; fa[i*4+3] = v.w;
    }
    vbh0 = *(const uint4*)(Bhp); vbh1 = *(const uint4*)(Bhp + 8);
    vbl0 = *(const uint4*)(Blp); vbl1 = *(const uint4*)(Blp + 8);

    const int nch = K >> 5;
    for (int c = 0; c < nch; c++) {
#pragma unroll
        for (int i = 0; i < 8; i++) {
            uint32_t hi, lo;
            split2(fa[2*i], fa[2*i+1], hi, lo);
            *(uint32_t*)&Ah[lr][lh + 2*i] = hi;
            *(uint32_t*)&Al[lr][lh + 2*i] = lo;
        }
        *(uint4*)&Bh[lr][lh]     = vbh0; *(uint4*)&Bh[lr][lh + 8] = vbh1;
        *(uint4*)&Bl[lr][lh]     = vbl0; *(uint4*)&Bl[lr][lh + 8] = vbl1;
        __syncthreads();
        if (c + 1 < nch) {
            const float* ap = Ap + (c + 1) * 32;
#pragma unroll
            for (int i = 0; i < 4; i++) {
                float4 v = *(const float4*)(ap + i * 4);
                fa[i*4+0] = v.x; fa[i*4+1] = v.y; fa[i*4+2] = v.z; fa[i*4+3] = v.w;
            }
            const __nv_bfloat16* bp = Bhp + (c + 1) * 32;
            const __nv_bfloat16* lp = Blp + (c + 1) * 32;
            vbh0 = *(const uint4*)(bp); vbh1 = *(const uint4*)(bp + 8);
            vbl0 = *(const uint4*)(lp); vbl1 = *(const uint4*)(lp + 8);
        }
#pragma unroll
        for (int s = 0; s < 2; s++) {
            const int k16 = s * 16;
            uint32_t bhf[4][2], blf[4][2];
#pragma unroll
            for (int njp = 0; njp < 2; njp++) {
                int n = wn + (njp * 2 + b_nj) * 8 + b_r;
                ldsm4(bhf[njp*2][0], bhf[njp*2][1], bhf[njp*2+1][0], bhf[njp*2+1][1],
                      &Bh[n][k16 + b_c]);
                ldsm4(blf[njp*2][0], blf[njp*2][1], blf[njp*2+1][0], blf[njp*2+1][1],
                      &Bl[n][k16 + b_c]);
            }
#pragma unroll
            for (int mi = 0; mi < 4; mi++) {
                int r = wm + mi * 16 + a_r;
                uint32_t ah[4], al[4];
                ldsm4(ah[0], ah[1], ah[2], ah[3], &Ah[r][k16 + a_c]);
                ldsm4(al[0], al[1], al[2], al[3], &Al[r][k16 + a_c]);
#pragma unroll
                for (int nj = 0; nj < 4; nj++) {
                    mma16816(acc[mi][nj], ah, bhf[nj]);
                    mma16816(acc[mi][nj], ah, blf[nj]);
                    mma16816(acc[mi][nj], al, bhf[nj]);
                }
            }
        }
        __syncthreads();
    }

#pragma unroll
    for (int mi = 0; mi < 4; mi++) {
        int row = rowBase + wm + mi * 16 + gr;
#pragma unroll
        for (int nj = 0; nj < 4; nj++) {
            int col = colBase + wn + nj * 8 + (lane & 3) * 2;
            float v0 = acc[mi][nj][0], v1 = acc[mi][nj][1];
            float v2 = acc[mi][nj][2], v3 = acc[mi][nj][3];
            if (BIASF) {
                float b0 = __ldg(bias + col), b1 = __ldg(bias + col + 1);
                v0 += b0; v1 += b1; v2 += b0; v3 += b1;
            }
            if (RELUF) {
                v0 = fmaxf(v0, 0.f); v1 = fmaxf(v1, 0.f);
                v2 = fmaxf(v2, 0.f); v3 = fmaxf(v3, 0.f);
            }
            if (RESID) {
                if (row >= PADN) {
                    float* a0 = C + (long)(row - PADN) * ldc + col;
                    float2 o = *(float2*)a0;
                    *(float2*)a0 = make_float2(v0 + o.x, v1 + o.y);
                }
                if (row + 8 >= PADN) {
                    float* a1 = C + (long)(row + 8 - PADN) * ldc + col;
                    float2 o = *(float2*)a1;
                    *(float2*)a1 = make_float2(v2 + o.x, v3 + o.y);
                }
            } else {
                *(float2*)(C + (long)row * ldc + col)       = make_float2(v0, v1);
                *(float2*)(C + (long)(row + 8) * ldc + col) = make_float2(v2, v3);
            }
        }
    }
}

template<bool BI, bool RE, bool RD>
static void TG(const float* A, const __nv_bfloat16* wb, const float* bias, float* C,
               int M, int N, int K, int lda, int ldc, long sAb, long sCb, int nbz)
{
    dim3 g(N >> 7, M >> 7, nbz);
    tgemm<BI, RE, RD><<<g, 256>>>(A, wb, wb + (long)N * K, bias, C, K, lda, ldc, sAb, sCb);
}

// ============ natural-layout GEMM (pinv/ZAV): C = alpha*A@B + diag*I ============
template<int BN>
__global__ void __launch_bounds__(256)
tg3(const float* __restrict__ A, const float* __restrict__ B, float* __restrict__ C,
    float* __restrict__ C2, int K, int lda, int ldb, int ldc,
    long sA1, long sB1, long sC,
    float alpha, float addDiag, float alpha2, float diag2)
{
    __shared__ __nv_bfloat16 Ah[64][40], Al[64][40];
    __shared__ __nv_bfloat16 Bkh[32][BN + 8], Bkl[32][BN + 8];
    const int tid = threadIdx.x, warp = tid >> 5, lane = tid & 31;
    int z = blockIdx.z;
    A += (long)z * sA1;
    B += (long)z * sB1;
    C += (long)z * sC;
    if (C2) C2 += (long)z * sC;
    const int rowBase = blockIdx.y << 6, colBase = blockIdx.x * BN;
    const int lr = tid >> 2, lh = (tid & 3) << 3;
    const float* Ap = A + (long)(rowBase + lr) * lda + lh;
    constexpr int BNV = BN / 8;
    const int bkr = tid >> 3, bn0 = (tid & 7) * BNV;
    const float* Bp = B + (long)bkr * ldb + colBase + bn0;
    constexpr int NJ = BN / 32;
    const int wm = (warp & 1) << 5, wn = (warp >> 1) * (BN / 4);
    const int gr = lane >> 2;
    const int a_r = (lane & 7) + ((lane >> 3) & 1) * 8, a_c = (lane >> 4) << 3;
    const int b_kr = (lane & 7) + ((lane >> 3) & 1) * 8, b_nc = (lane >> 4) << 3;

    float acc[2][NJ][4];
#pragma unroll
    for (int i = 0; i < 2; i++)
#pragma unroll
        for (int j = 0; j < NJ; j++)
#pragma unroll
            for (int t = 0; t < 4; t++) acc[i][j][t] = 0.f;

    float fa[8], fb[BNV];
#pragma unroll
    for (int i = 0; i < 2; i++) {
        float4 v = *(const float4*)(Ap + i * 4);
        fa[i*4+0] = v.x; fa[i*4+1] = v.y; fa[i*4+2] = v.z; fa[i*4+3] = v.w;
    }
#pragma unroll
    for (int i = 0; i < BNV / 4; i++) {
        float4 v = *(const float4*)(Bp + i * 4);
        fb[i*4+0] = v.x; fb[i*4+1] = v.y; fb[i*4+2] = v.z; fb[i*4+3] = v.w;
    }

    const int nch = K >> 5;
    for (int c = 0; c < nch; c++) {
#pragma unroll
        for (int i = 0; i < 4; i++) {
            uint32_t hi, lo;
            split2(fa[2*i], fa[2*i+1], hi, lo);
            *(uint32_t*)&Ah[lr][lh + 2*i] = hi;
            *(uint32_t*)&Al[lr][lh + 2*i] = lo;
        }
#pragma unroll
        for (int i = 0; i < BNV / 2; i++) {
            uint32_t hi, lo;
            split2(fb[2*i], fb[2*i+1], hi, lo);
            *(uint32_t*)&Bkh[bkr][bn0 + 2*i] = hi;
            *(uint32_t*)&Bkl[bkr][bn0 + 2*i] = lo;
        }
        __syncthreads();
        if (c + 1 < nch) {
            const float* ap = Ap + (c + 1) * 32;
#pragma unroll
            for (int i = 0; i < 2; i++) {
                float4 v = *(const float4*)(ap + i * 4);
                fa[i*4+0] = v.x; fa[i*4+1] = v.y; fa[i*4+2] = v.z; fa[i*4+3] = v.w;
            }
            const float* bp = Bp + (long)(c + 1) * 32 * ldb;
#pragma unroll
            for (int i = 0; i < BNV / 4; i++) {
                float4 v = *(const float4*)(bp + i * 4);
                fb[i*4+0] = v.x; fb[i*4+1] = v.y; fb[i*4+2] = v.z; fb[i*4+3] = v.w;
            }
        }
#pragma unroll
        for (int s = 0; s < 2; s++) {
            const int k16 = s * 16;
            uint32_t bhf[NJ][2], blf[NJ][2];
#pragma unroll
            for (int njp = 0; njp < NJ / 2; njp++) {
                int n = wn + njp * 16 + b_nc;
                ldsm4t(bhf[njp*2][0], bhf[njp*2][1], bhf[njp*2+1][0], bhf[njp*2+1][1],
                       &Bkh[k16 + b_kr][n]);
                ldsm4t(blf[njp*2][0], blf[njp*2][1], blf[njp*2+1][0], blf[njp*2+1][1],
                       &Bkl[k16 + b_kr][n]);
            }
#pragma unroll
            for (int mi = 0; mi < 2; mi++) {
                int r = wm + mi * 16 + a_r;
                uint32_t ah[4], al[4];
                ldsm4(ah[0], ah[1], ah[2], ah[3], &Ah[r][k16 + a_c]);
                ldsm4(al[0], al[1], al[2], al[3], &Al[r][k16 + a_c]);
#pragma unroll
                for (int nj = 0; nj < NJ; nj++) {
                    mma16816(acc[mi][nj], ah, bhf[nj]);
                    mma16816(acc[mi][nj], ah, blf[nj]);
                    mma16816(acc[mi][nj], al, bhf[nj]);
                }
            }
        }
        __syncthreads();
    }

#pragma unroll
    for (int mi = 0; mi < 2; mi++) {
        int row = rowBase + wm + mi * 16 + gr;
#pragma unroll
        for (int nj = 0; nj < NJ; nj++) {
            int col = colBase + wn + nj * 8 + (lane & 3) * 2;
            float a0 = acc[mi][nj][0], a1 = acc[mi][nj][1];
            float a2 = acc[mi][nj][2], a3 = acc[mi][nj][3];
            float v0 = alpha * a0 + ((row == col)     ? addDiag : 0.f);
            float v1 = alpha * a1 + ((row == col + 1) ? addDiag : 0.f);
            float v2 = alpha * a2 + ((row + 8 == col)     ? addDiag : 0.f);
            float v3 = alpha * a3 + ((row + 8 == col + 1) ? addDiag : 0.f);
            *(float2*)(C + (long)row * ldc + col)       = make_float2(v0, v1);
            *(float2*)(C + (long)(row + 8) * ldc + col) = make_float2(v2, v3);
            if (C2) {
                float w0 = alpha2 * a0 + ((row == col)     ? diag2 : 0.f);
                float w1 = alpha2 * a1 + ((row == col + 1) ? diag2 : 0.f);
                float w2 = alpha2 * a2 + ((row + 8 == col)     ? diag2 : 0.f);
                float w3 = alpha2 * a3 + ((row + 8 == col + 1) ? diag2 : 0.f);
                *(float2*)(C2 + (long)row * ldc + col)       = make_float2(w0, w1);
                *(float2*)(C2 + (long)(row + 8) * ldc + col) = make_float2(w2, w3);
            }
        }
    }
}

template<int BN>
static void TG3(const float* A, const float* B, float* C, float* C2,
                int M, int N, int K, int lda, int ldb, int ldc,
                long sA1, long sB1, long sC, int nz,
                float alpha, float addDiag, float alpha2, float diag2, cudaStream_t st)
{
    dim3 g(N / BN, M >> 6, nz);
    tg3<BN><<<g, 256, 0, st>>>(A, B, C, C2, K, lda, ldb, ldc, sA1, sB1, sC,
                               alpha, addDiag, alpha2, diag2);
}

// ============ flash attn3: AVP/m/s partials = online-softmax(QSCALE*QL@K^T) @ V ============
#define F3_SMEM (8*9216 + 2048)
__global__ void __launch_bounds__(256)
flash3(const float* __restrict__ QKV, const float* __restrict__ QL,
       float* __restrict__ AVP, float* __restrict__ MM, float* __restrict__ SS)
{
    extern __shared__ char sm_[];
    __nv_bfloat16 (*Qh)[72] = (__nv_bfloat16(*)[72])(sm_);
    __nv_bfloat16 (*Qlw)[72] = (__nv_bfloat16(*)[72])(sm_ + 9216);
    __nv_bfloat16 (*Kh)[72] = (__nv_bfloat16(*)[72])(sm_ + 18432);
    __nv_bfloat16 (*Kl)[72] = (__nv_bfloat16(*)[72])(sm_ + 27648);
    __nv_bfloat16 (*Vh)[72] = (__nv_bfloat16(*)[72])(sm_ + 36864);
    __nv_bfloat16 (*Vl)[72] = (__nv_bfloat16(*)[72])(sm_ + 46080);
    __nv_bfloat16 (*Ph)[72] = (__nv_bfloat16(*)[72])(sm_ + 55296);
    __nv_bfloat16 (*Pl)[72] = (__nv_bfloat16(*)[72])(sm_ + 64512);
    float* red = (float*)(sm_ + 73728);
    const int tid = threadIdx.x, warp = tid >> 5, lane = tid & 31;
    const int l2 = lane & 3, gr = lane >> 2;
    const int ns = blockIdx.x, rb = blockIdx.y, z = blockIdx.z;
    const int b = z >> 3, h = z & 7;
    const int wm = (warp & 1) << 5, cg = warp >> 1, wn = cg << 4;
    const int a_r = (lane & 7) + ((lane >> 3) & 1) * 8, a_c = (lane >> 4) << 3;
    const int b_r = lane & 7, b_nj = (lane >> 4) & 1, b_c = ((lane >> 3) & 1) << 3;
    const int b_kr = (lane & 7) + ((lane >> 3) & 1) * 8, b_nc = (lane >> 4) << 3;
    const int lr = tid >> 2, lh = (tid & 3) << 4;

    {
        const float* qp = QL + (long)z * LM * DH + (long)(rb * 64 + lr) * DH + lh;
#pragma unroll
        for (int i = 0; i < 4; i++) {
            float4 v = *(const float4*)(qp + i * 4);
            uint32_t hi, lo;
            split2(v.x, v.y, hi, lo);
            *(uint32_t*)&Qh[lr][lh + i*4]     = hi; *(uint32_t*)&Qlw[lr][lh + i*4]     = lo;
            split2(v.z, v.w, hi, lo);
            *(uint32_t*)&Qh[lr][lh + i*4 + 2] = hi; *(uint32_t*)&Qlw[lr][lh + i*4 + 2] = lo;
        }
    }
    float accav[2][2][4];
    float mrun[2][2], srun[2][2];
#pragma unroll
    for (int i = 0; i < 2; i++)
#pragma unroll
        for (int t = 0; t < 2; t++) { mrun[i][t] = -3.0e38f; srun[i][t] = 0.f; }
#pragma unroll
    for (int i = 0; i < 2; i++)
#pragma unroll
        for (int j = 0; j < 2; j++)
#pragma unroll
            for (int t = 0; t < 4; t++) accav[i][j][t] = 0.f;

    const float* kvb = QKV + (long)b * NPD * D3 + h * DH;
    for (int c = 0; c < 26; c++) {
        long tb = (long)ns * KCH + c * 64;
        {
            const float* kp = kvb + (tb + lr) * D3 + DD + lh;
            const float* vp = kvb + (tb + lr) * D3 + 2 * DD + lh;
#pragma unroll
            for (int i = 0; i < 4; i++) {
                float4 v = *(const float4*)(kp + i * 4);
                uint32_t hi, lo;
                split2(v.x, v.y, hi, lo);
                *(uint32_t*)&Kh[lr][lh + i*4]     = hi; *(uint32_t*)&Kl[lr][lh + i*4]     = lo;
                split2(v.z, v.w, hi, lo);
                *(uint32_t*)&Kh[lr][lh + i*4 + 2] = hi; *(uint32_t*)&Kl[lr][lh + i*4 + 2] = lo;
                float4 w = *(const float4*)(vp + i * 4);
                split2(w.x, w.y, hi, lo);
                *(uint32_t*)&Vh[lr][lh + i*4]     = hi; *(uint32_t*)&Vl[lr][lh + i*4]     = lo;
                split2(w.z, w.w, hi, lo);
                *(uint32_t*)&Vh[lr][lh + i*4 + 2] = hi; *(uint32_t*)&Vl[lr][lh + i*4 + 2] = lo;
            }
        }
        __syncthreads();
        float acc[2][2][4];
#pragma unroll
        for (int i = 0; i < 2; i++)
#pragma unroll
            for (int j = 0; j < 2; j++)
#pragma unroll
                for (int t = 0; t < 4; t++) acc[i][j][t] = 0.f;
#pragma unroll
        for (int s = 0; s < 4; s++) {
            const int k16 = s * 16;
            uint32_t bhf[2][2], blf[2][2];
            {
                int n = wn + b_nj * 8 + b_r;
                ldsm4(bhf[0][0], bhf[0][1], bhf[1][0], bhf[1][1], &Kh[n][k16 + b_c]);
                ldsm4(blf[0][0], blf[0][1], blf[1][0], blf[1][1], &Kl[n][k16 + b_c]);
            }
#pragma unroll
            for (int mi = 0; mi < 2; mi++) {
                int r = wm + mi * 16 + a_r;
                uint32_t ah[4], al[4];
                ldsm4(ah[0], ah[1], ah[2], ah[3], &Qh[r][k16 + a_c]);
                ldsm4(al[0], al[1], al[2], al[3], &Qlw[r][k16 + a_c]);
#pragma unroll
                for (int nj = 0; nj < 2; nj++) {
                    mma16816(acc[mi][nj], ah, bhf[nj]);
                    mma16816(acc[mi][nj], ah, blf[nj]);
                    mma16816(acc[mi][nj], al, bhf[nj]);
                }
            }
        }
#pragma unroll
        for (int mi = 0; mi < 2; mi++)
#pragma unroll
            for (int nj = 0; nj < 2; nj++)
#pragma unroll
                for (int t = 0; t < 4; t++) acc[mi][nj][t] *= QSCALE;
#pragma unroll
        for (int mi = 0; mi < 2; mi++)
#pragma unroll
            for (int t = 0; t < 2; t++) {
                float m = fmaxf(fmaxf(acc[mi][0][2*t], acc[mi][0][2*t+1]),
                                fmaxf(acc[mi][1][2*t], acc[mi][1][2*t+1]));
                m = fmaxf(m, __shfl_xor_sync(0xffffffffu, m, 1));
                m = fmaxf(m, __shfl_xor_sync(0xffffffffu, m, 2));
                red[(wm + mi * 16 + gr + t * 8) * 4 + cg] = m;
            }
        __syncthreads();
#pragma unroll
        for (int mi = 0; mi < 2; mi++)
#pragma unroll
            for (int t = 0; t < 2; t++) {
                const float* r4 = red + (wm + mi * 16 + gr + t * 8) * 4;
                float mc = fmaxf(fmaxf(r4[0], r4[1]), fmaxf(r4[2], r4[3]));
                float mnew = fmaxf(mrun[mi][t], mc);
                float f = __expf(mrun[mi][t] - mnew);
                mrun[mi][t] = mnew;
                float sc = 0.f;
#pragma unroll
                for (int nj = 0; nj < 2; nj++) {
                    float e0 = __expf(acc[mi][nj][2*t]   - mnew);
                    float e1 = __expf(acc[mi][nj][2*t+1] - mnew);
                    acc[mi][nj][2*t] = e0; acc[mi][nj][2*t+1] = e1;
                    sc += e0 + e1;
                    accav[mi][nj][2*t] *= f; accav[mi][nj][2*t+1] *= f;
                }
                sc += __shfl_xor_sync(0xffffffffu, sc, 1);
                sc += __shfl_xor_sync(0xffffffffu, sc, 2);
                srun[mi][t] = srun[mi][t] * f + sc;
                int row = wm + mi * 16 + gr + t * 8;
#pragma unroll
                for (int nj = 0; nj < 2; nj++) {
                    int col = wn + nj * 8 + l2 * 2;
                    uint32_t hi, lo;
                    split2(acc[mi][nj][2*t], acc[mi][nj][2*t+1], hi, lo);
                    *(uint32_t*)&Ph[row][col] = hi;
                    *(uint32_t*)&Pl[row][col] = lo;
                }
            }
        __syncthreads();
#pragma unroll
        for (int s = 0; s < 4; s++) {
            const int k16 = s * 16;
            uint32_t bhf[2][2], blf[2][2];
            ldsm4t(bhf[0][0], bhf[0][1], bhf[1][0], bhf[1][1], &Vh[k16 + b_kr][wn + b_nc]);
            ldsm4t(blf[0][0], blf[0][1], blf[1][0], blf[1][1], &Vl[k16 + b_kr][wn + b_nc]);
#pragma unroll
            for (int mi = 0; mi < 2; mi++) {
                int r = wm + mi * 16 + a_r;
                uint32_t ah[4], al[4];
                ldsm4(ah[0], ah[1], ah[2], ah[3], &Ph[r][k16 + a_c]);
                ldsm4(al[0], al[1], al[2], al[3], &Pl[r][k16 + a_c]);
#pragma unroll
                for (int nj = 0; nj < 2; nj++) {
                    mma16816(accav[mi][nj], ah, bhf[nj]);
                    mma16816(accav[mi][nj], ah, blf[nj]);
                    mma16816(accav[mi][nj], al, bhf[nj]);
                }
            }
        }
        __syncthreads();
    }

#pragma unroll
    for (int mi = 0; mi < 2; mi++)
#pragma unroll
        for (int t = 0; t < 2; t++) {
            if (l2 == 0) red[(wm + mi * 16 + gr + t * 8) * 4 + cg] = srun[mi][t];
        }
    __syncthreads();
    float* avp = AVP + (((long)z * NSPL + ns) * LM + rb * 64) * DH;
#pragma unroll
    for (int mi = 0; mi < 2; mi++)
#pragma unroll
        for (int t = 0; t < 2; t++) {
            int row = wm + mi * 16 + gr + t * 8;
#pragma unroll
            for (int nj = 0; nj < 2; nj++) {
                int col = wn + nj * 8 + l2 * 2;
                *(float2*)(avp + (long)row * DH + col) =
                    make_float2(accav[mi][nj][2*t], accav[mi][nj][2*t+1]);
            }
            if (cg == 0 && l2 == 0) {
                const float* r4 = red + row * 4;
                long mi_idx = ((long)z * NSPL + ns) * LM + rb * 64 + row;
                MM[mi_idx] = mrun[mi][t];
                SS[mi_idx] = r4[0] + r4[1] + r4[2] + r4[3];
            }
        }
}

__global__ void f3comb(const float* __restrict__ AVP, const float* __restrict__ MM,
                       const float* __restrict__ SS, float* __restrict__ AV)
{
    int idx = blockIdx.x * 256 + threadIdx.x;
    int z = idx >> 14, r = (idx >> 6) & 255, d = idx & 63;
    long mbase = (long)z * NSPL * LM + r;
    float m = -3.0e38f;
#pragma unroll
    for (int ns = 0; ns < NSPL; ns++) m = fmaxf(m, __ldg(MM + mbase + (long)ns * LM));
    float s = 0.f, a = 0.f;
#pragma unroll
    for (int ns = 0; ns < NSPL; ns++) {
        float e = __expf(__ldg(MM + mbase + (long)ns * LM) - m);
        s += __ldg(SS + mbase + (long)ns * LM) * e;
        a += __ldg(AVP + ((long)(z * NSPL + ns) * LM + r) * DH + d) * e;
    }
    AV[idx] = a / s;
}

// ============ fused attn1 + softmax + @ZAV (flash-style) ============
#define A1OH_SMEM 76800
__global__ void __launch_bounds__(256)
attn1oh(const float* __restrict__ QKV, const float* __restrict__ KL,
        const float* __restrict__ ZAV, float* __restrict__ OH)
{
    extern __shared__ char sm_[];
    const int tid = threadIdx.x, warp = tid >> 5, lane = tid & 31;
    const int l2 = lane & 3, gr = lane >> 2;
    int z = blockIdx.y, b = z >> 3, h = z & 7;
    const int rowBase = blockIdx.x << 6;
    const float* Qp = QKV + (long)b * NPD * D3 + h * DH;
    KL += (long)z * LM * DH;
    ZAV += (long)z * LM * DH;
    OH += (long)z * NPD * DH;
    const int a_r = (lane & 7) + ((lane >> 3) & 1) * 8, a_c = (lane >> 4) << 3;
    const int b_r = lane & 7, b_nj = (lane >> 4) & 1, b_c = ((lane >> 3) & 1) << 3;

    const int rg = warp & 1, cg = warp >> 1;
    const int wm1 = rg << 5, wn1 = cg << 6;
    __nv_bfloat16 (*Ah)[40] = (__nv_bfloat16(*)[40])(sm_);
    __nv_bfloat16 (*Al)[40] = (__nv_bfloat16(*)[40])(sm_ + 5120);
    __nv_bfloat16 (*Bh)[40] = (__nv_bfloat16(*)[40])(sm_ + 10240);
    __nv_bfloat16 (*Bl)[40] = (__nv_bfloat16(*)[40])(sm_ + 30720);

    float acc[2][8][4];
#pragma unroll
    for (int i = 0; i < 2; i++)
#pragma unroll
        for (int j = 0; j < 8; j++)
#pragma unroll
            for (int t = 0; t < 4; t++) acc[i][j][t] = 0.f;

    const int lr = tid >> 2, lh = (tid & 3) << 3;
    for (int c = 0; c < 2; c++) {
        const float* ap = Qp + (long)(rowBase + lr) * D3 + c * 32 + lh;
#pragma unroll
        for (int i = 0; i < 2; i++) {
            float4 v = *(const float4*)(ap + i * 4);
            uint32_t hi, lo;
            split2(v.x, v.y, hi, lo);
            *(uint32_t*)&Ah[lr][lh + i*4]     = hi; *(uint32_t*)&Al[lr][lh + i*4]     = lo;
            split2(v.z, v.w, hi, lo);
            *(uint32_t*)&Ah[lr][lh + i*4 + 2] = hi; *(uint32_t*)&Al[lr][lh + i*4 + 2] = lo;
        }
        const float* bp = KL + (long)tid * DH + c * 32;
#pragma unroll
        for (int i = 0; i < 8; i++) {
            float4 v = *(const float4*)(bp + i * 4);
            uint32_t hi, lo;
            split2(v.x, v.y, hi, lo);
            *(uint32_t*)&Bh[tid][i*4]     = hi; *(uint32_t*)&Bl[tid][i*4]     = lo;
            split2(v.z, v.w, hi, lo);
            *(uint32_t*)&Bh[tid][i*4 + 2] = hi; *(uint32_t*)&Bl[tid][i*4 + 2] = lo;
        }
        __syncthreads();
#pragma unroll
        for (int s = 0; s < 2; s++) {
            const int k16 = s * 16;
            uint32_t bhf[8][2], blf[8][2];
#pragma unroll
            for (int njp = 0; njp < 4; njp++) {
                int n = wn1 + (njp * 2 + b_nj) * 8 + b_r;
                ldsm4(bhf[njp*2][0], bhf[njp*2][1], bhf[njp*2+1][0], bhf[njp*2+1][1],
                      &Bh[n][k16 + b_c]);
                ldsm4(blf[njp*2][0], blf[njp*2][1], blf[njp*2+1][0], blf[njp*2+1][1],
                      &Bl[n][k16 + b_c]);
            }
#pragma unroll
            for (int mi = 0; mi < 2; mi++) {
                int r = wm1 + mi * 16 + a_r;
                uint32_t ah[4], al[4];
                ldsm4(ah[0], ah[1], ah[2], ah[3], &Ah[r][k16 + a_c]);
                ldsm4(al[0], al[1], al[2], al[3], &Al[r][k16 + a_c]);
#pragma unroll
                for (int nj = 0; nj < 8; nj++) {
                    mma16816(acc[mi][nj], ah, bhf[nj]);
                    mma16816(acc[mi][nj], ah, blf[nj]);
                    mma16816(acc[mi][nj], al, bhf[nj]);
                }
            }
        }
        __syncthreads();
    }

#pragma unroll
    for (int i = 0; i < 2; i++)
#pragma unroll
        for (int j = 0; j < 8; j++)
#pragma unroll
            for (int t = 0; t < 4; t++) acc[i][j][t] *= QSCALE;

    float* red = (float*)sm_;
    float gmax[2][2], ginv[2][2];
#pragma unroll
    for (int mi = 0; mi < 2; mi++)
#pragma unroll
        for (int t = 0; t < 2; t++) {
            float m = -3.0e38f;
#pragma unroll
            for (int nj = 0; nj < 8; nj++)
                m = fmaxf(m, fmaxf(acc[mi][nj][2*t], acc[mi][nj][2*t+1]));
            m = fmaxf(m, __shfl_xor_sync(0xffffffffu, m, 1));
            m = fmaxf(m, __shfl_xor_sync(0xffffffffu, m, 2));
            red[(wm1 + mi * 16 + gr + t * 8) * 4 + cg] = m;
        }
    __syncthreads();
#pragma unroll
    for (int mi = 0; mi < 2; mi++)
#pragma unroll
        for (int t = 0; t < 2; t++) {
            const float* r4 = red + (wm1 + mi * 16 + gr + t * 8) * 4;
            gmax[mi][t] = fmaxf(fmaxf(r4[0], r4[1]), fmaxf(r4[2], r4[3]));
        }
    __syncthreads();
    float* red2 = red + 64 * 4;
#pragma unroll
    for (int mi = 0; mi < 2; mi++)
#pragma unroll
        for (int t = 0; t < 2; t++) {
            float s = 0.f;
#pragma unroll
            for (int nj = 0; nj < 8; nj++) {
                float e0 = __expf(acc[mi][nj][2*t]   - gmax[mi][t]);
                float e1 = __expf(acc[mi][nj][2*t+1] - gmax[mi][t]);
                acc[mi][nj][2*t] = e0; acc[mi][nj][2*t+1] = e1;
                s += e0 + e1;
            }
            s += __shfl_xor_sync(0xffffffffu, s, 1);
            s += __shfl_xor_sync(0xffffffffu, s, 2);
            red2[(wm1 + mi * 16 + gr + t * 8) * 4 + cg] = s;
        }
    __syncthreads();
#pragma unroll
    for (int mi = 0; mi < 2; mi++)
#pragma unroll
        for (int t = 0; t < 2; t++) {
            const float* r4 = red2 + (wm1 + mi * 16 + gr + t * 8) * 4;
            ginv[mi][t] = 1.f / (r4[0] + r4[1] + r4[2] + r4[3]);
        }
    __syncthreads();

    __nv_bfloat16 (*Ph)[264] = (__nv_bfloat16(*)[264])(sm_);
    __nv_bfloat16 (*Pl)[264] = (__nv_bfloat16(*)[264])(sm_ + 33792);
#pragma unroll
    for (int mi = 0; mi < 2; mi++)
#pragma unroll
        for (int t = 0; t < 2; t++) {
            int row = wm1 + mi * 16 + gr + t * 8;
#pragma unroll
            for (int nj = 0; nj < 8; nj++) {
                int col = wn1 + nj * 8 + l2 * 2;
                uint32_t hi, lo;
                split2(acc[mi][nj][2*t] * ginv[mi][t], acc[mi][nj][2*t+1] * ginv[mi][t], hi, lo);
                *(uint32_t*)&Ph[row][col] = hi;
                *(uint32_t*)&Pl[row][col] = lo;
            }
        }
    __syncthreads();

    const int wm3 = (warp & 1) << 5, wn3 = (warp >> 1) << 4;
    __nv_bfloat16 (*Bzh)[72] = (__nv_bfloat16(*)[72])(sm_ + 67584);
    __nv_bfloat16 (*Bzl)[72] = (__nv_bfloat16(*)[72])(sm_ + 67584 + 4608);
    const int zr = tid >> 3, zc = (tid & 7) << 3;
    float oacc[2][2][4];
#pragma unroll
    for (int i = 0; i < 2; i++)
#pragma unroll
        for (int j = 0; j < 2; j++)
#pragma unroll
            for (int t = 0; t < 4; t++) oacc[i][j][t] = 0.f;

    for (int kc = 0; kc < 8; kc++) {
        const float* zp = ZAV + (long)(kc * 32 + zr) * DH + zc;
#pragma unroll
        for (int i = 0; i < 2; i++) {
            float4 v = *(const float4*)(zp + i * 4);
            uint32_t hi, lo;
            split2(v.x, v.y, hi, lo);
            *(uint32_t*)&Bzh[zr][zc + i*4]     = hi; *(uint32_t*)&Bzl[zr][zc + i*4]     = lo;
            split2(v.z, v.w, hi, lo);
            *(uint32_t*)&Bzh[zr][zc + i*4 + 2] = hi; *(uint32_t*)&Bzl[zr][zc + i*4 + 2] = lo;
        }
        __syncthreads();
#pragma unroll
        for (int s = 0; s < 2; s++) {
            const int k16l = s * 16, k16g = kc * 32 + s * 16;
            uint32_t bhf[2][2], blf[2][2];
            ldsm4t(bhf[0][0], bhf[0][1], bhf[1][0], bhf[1][1],
                   &Bzh[k16l + (lane & 7) + ((lane >> 3) & 1) * 8][wn3 + ((lane >> 4) << 3)]);
            ldsm4t(blf[0][0], blf[0][1], blf[1][0], blf[1][1],
                   &Bzl[k16l + (lane & 7) + ((lane >> 3) & 1) * 8][wn3 + ((lane >> 4) << 3)]);
#pragma unroll
            for (int mi = 0; mi < 2; mi++) {
                int r = wm3 + mi * 16 + a_r;
                uint32_t ah[4], al[4];
                ldsm4(ah[0], ah[1], ah[2], ah[3], &Ph[r][k16g + a_c]);
                ldsm4(al[0], al[1], al[2], al[3], &Pl[r][k16g + a_c]);
#pragma unroll
                for (int nj = 0; nj < 2; nj++) {
                    mma16816(oacc[mi][nj], ah, bhf[nj]);
                    mma16816(oacc[mi][nj], ah, blf[nj]);
                    mma16816(oacc[mi][nj], al, bhf[nj]);
                }
            }
        }
        __syncthreads();
    }

#pragma unroll
    for (int mi = 0; mi < 2; mi++) {
        long row = rowBase + wm3 + mi * 16 + gr;
#pragma unroll
        for (int nj = 0; nj < 2; nj++) {
            int col = wn3 + nj * 8 + l2 * 2;
            *(float2*)(OH + row * DH + col)       = make_float2(oacc[mi][nj][0], oacc[mi][nj][1]);
            *(float2*)(OH + (row + 8) * DH + col) = make_float2(oacc[mi][nj][2], oacc[mi][nj][3]);
        }
    }
}

// weight prep
__global__ void wprep(const float* __restrict__ W, __nv_bfloat16* __restrict__ out, int K, int N) {
    long idx = (long)blockIdx.x * 256 + threadIdx.x;
    if (idx >= (long)K * N) return;
    int n = (int)(idx / K), k = (int)(idx - (long)n * K);
    float v = __ldg(W + (long)k * N + n);
    __nv_bfloat16 h = __float2bfloat16(v);
    out[idx] = h;
    out[(long)N * K + idx] = __float2bfloat16(v - __bfloat162float(h));
}

// ---------------- helpers ----------------
template<int V>
__device__ __forceinline__ void ldv(float* r, const float* __restrict__ p) {
    if constexpr (V == 2) { float2 t = *(const float2*)p; r[0]=t.x; r[1]=t.y; }
    else if constexpr (V == 4) { float4 t = *(const float4*)p; r[0]=t.x; r[1]=t.y; r[2]=t.z; r[3]=t.w; }
    else if constexpr (V == 8) { ldv<4>(r, p); ldv<4>(r + 4, p + 4); }
}
__device__ __forceinline__ float brsum(float v, float* shm) {
    int lane = threadIdx.x & 31, wid = threadIdx.x >> 5;
#pragma unroll
    for (int o = 16; o; o >>= 1) v += __shfl_xor_sync(0xffffffffu, v, o);
    __syncthreads();
    if (lane == 0) shm[wid] = v;
    __syncthreads();
    int nw = blockDim.x >> 5;
    float r = (threadIdx.x < nw) ? shm[threadIdx.x] : 0.f;
    if (wid == 0) {
#pragma unroll
        for (int o = 16; o; o >>= 1) r += __shfl_xor_sync(0xffffffffu, r, o);
        if (lane == 0) shm[0] = r;
    }
    __syncthreads();
    return shm[0];
}

// ---------------- fused GEMM + row softmax (attn2 only) ----------------
__global__ void __launch_bounds__(256)
attn_sm_kernel(const float* __restrict__ A, const float* __restrict__ B,
               float* __restrict__ C, int lda, long sAb, long sAh, long sCz)
{
    int z = blockIdx.y, b = z >> 3, h = z & 7;
    A += (long)b * sAb + (long)h * sAh;
    B += (long)z * (LM * DH);
    C += (long)z * sCz;
    __shared__ float As[2][8][64];
    __shared__ float Bs[2][8][256];
    const int tid = threadIdx.x, tx = tid & 15, ty = tid >> 4;
    const int rowBase = blockIdx.x * 64;
    const int arow = tid >> 2, acol = (tid & 3) * 2;
    const float* Ap = A + (long)(rowBase + arow) * lda + acol;
    const float* Bp = B + tid * DH;
    float ra[2], rb[8];
    float acc[4][16];
#pragma unroll
    for (int i = 0; i < 4; i++)
#pragma unroll
        for (int j = 0; j < 16; j++) acc[i][j] = 0.f;

    ldv<2>(ra, Ap);
    ldv<8>(rb, Bp);
    As[0][acol][arow] = ra[0]; As[0][acol + 1][arow] = ra[1];
#pragma unroll
    for (int i = 0; i < 8; i++) Bs[0][i][tid] = rb[i];
    __syncthreads();

    for (int kb = 0; kb < 8; kb++) {
        int cur = kb & 1;
        if (kb + 1 < 8) { ldv<2>(ra, Ap + (kb + 1) * 8); ldv<8>(rb, Bp + (kb + 1) * 8); }
#pragma unroll
        for (int k = 0; k < 8; k++) {
            float a[4], bv[16];
#pragma unroll
            for (int i = 0; i < 4; i++) a[i] = As[cur][k][ty * 4 + i];
#pragma unroll
            for (int j = 0; j < 16; j++) bv[j] = Bs[cur][k][tx * 16 + j];
#pragma unroll
            for (int i = 0; i < 4; i++)
#pragma unroll
                for (int j = 0; j < 16; j++) acc[i][j] += a[i] * bv[j];
        }
        if (kb + 1 < 8) {
            int nxt = cur ^ 1;
            As[nxt][acol][arow] = ra[0]; As[nxt][acol + 1][arow] = ra[1];
#pragma unroll
            for (int i = 0; i < 8; i++) Bs[nxt][i][tid] = rb[i];
        }
        __syncthreads();
    }

#pragma unroll
    for (int i = 0; i < 4; i++) {
        float m = -3.0e38f;
#pragma unroll
        for (int j = 0; j < 16; j++) { acc[i][j] *= QSCALE; m = fmaxf(m, acc[i][j]); }
#pragma unroll
        for (int o = 8; o; o >>= 1) m = fmaxf(m, __shfl_xor_sync(0xffffffffu, m, o));
        float s = 0.f;
#pragma unroll
        for (int j = 0; j < 16; j++) { float e = __expf(acc[i][j] - m); acc[i][j] = e; s += e; }
#pragma unroll
        for (int o = 8; o; o >>= 1) s += __shfl_xor_sync(0xffffffffu, s, o);
        float inv = 1.f / s;
        int row = rowBase + ty * 4 + i;
        float* crow = C + (long)row * LM + tx * 16;
#pragma unroll
        for (int j = 0; j < 16; j += 4) {
            float4 o = make_float4(acc[i][j] * inv, acc[i][j+1] * inv, acc[i][j+2] * inv, acc[i][j+3] * inv);
            *(float4*)(crow + j) = o;
        }
    }
}

// ---------------- small kernels ----------------
__global__ void cls_kernel(float* H, const float* cls) {
    int i = blockIdx.x * 256 + threadIdx.x;
    if (i >= BB * DD) return;
    int b = i / DD, c = i - b * DD;
    H[(long)b * NC * DD + c] = cls[c];
}
__global__ void h2cls_kernel(const float* __restrict__ H, float* __restrict__ H2) {
    int i = blockIdx.x * 256 + threadIdx.x;
    if (i >= BB * DD) return;
    int b = i / DD, c = i - b * DD;
    H2[(long)b * NC * DD + c] = H[(long)b * NC * DD + c];
}
__global__ void zero_pads_kernel(float* xln) {
    int idx = blockIdx.x * 256 + threadIdx.x;
    int b = idx / (PADN * DD), r = idx - b * (PADN * DD);
    xln[(long)b * NPD * DD + r] = 0.f;
}
__global__ void ln_kernel(const float* __restrict__ H, const float* __restrict__ g,
                          const float* __restrict__ be, float* __restrict__ out) {
    __shared__ float shm[32];
    int t = blockIdx.x, b = t / NC, tt = t - b * NC;
    const float* row = H + ((long)b * NC + tt) * DD;
    float* orow = out + ((long)b * NPD + PADN + tt) * DD;
    int c0 = threadIdx.x * 4;
    float4 v = *(const float4*)(row + c0);
    float mu = brsum(v.x + v.y + v.z + v.w, shm) * (1.f / DD);
    float d0 = v.x-mu, d1 = v.y-mu, d2 = v.z-mu, d3 = v.w-mu;
    float var = brsum(d0*d0 + d1*d1 + d2*d2 + d3*d3, shm) * (1.f / DD);
    float r = rsqrtf(var + 1e-5f);
    float4 gg = *(const float4*)(g + c0), bb = *(const float4*)(be + c0);
    float4 o = {d0*r*gg.x+bb.x, d1*r*gg.y+bb.y, d2*r*gg.z+bb.z, d3*r*gg.w+bb.w};
    *(float4*)(orow + c0) = o;
}
__global__ void landmark_kernel(const float* __restrict__ qkv, float* __restrict__ ql,
                                float* __restrict__ kl) {
    int i = blockIdx.x, z = blockIdx.y, d = threadIdx.x;
    int b = z >> 3, h = z & 7;
    const float* base = qkv + (long)b * NPD * D3 + (long)i * LCH * D3 + h * DH + d;
    float sq = 0.f, sk = 0.f;
    for (int j = 0; j < LCH; j++) { sq += base[(long)j * D3]; sk += base[(long)j * D3 + DD]; }
    ql[((long)z * LM + i) * DH + d] = sq * (1.f / LCH);
    kl[((long)z * LM + i) * DH + d] = sk * (1.f / LCH);
}
__global__ void zero_sc_kernel(int* sc) { if (threadIdx.x < 2) sc[threadIdx.x] = 0; }
__global__ void pinv_norm_kernel(const float* __restrict__ a2, int* mr, int* mc) {
    int z = blockIdx.x, t = threadIdx.x;
    const float* A = a2 + (long)z * LM * LM;
    float rs = 0.f, cs = 0.f;
    for (int j = 0; j < LM; j++) { rs += A[t * LM + j]; cs += A[j * LM + t]; }
    atomicMax(mr, __float_as_int(rs));
    atomicMax(mc, __float_as_int(cs));
}
__global__ void pinv_init_kernel(const float* __restrict__ a2, float* __restrict__ z0,
                                 const int* __restrict__ sc) {
    float inv = 1.f / (__int_as_float(sc[0]) * __int_as_float(sc[1]));
    long idx = (long)blockIdx.x * 256 + threadIdx.x;
    long zz = idx >> 16;
    int i = (int)((idx >> 8) & 255), j = (int)(idx & 255);
    z0[idx] = a2[(zz << 16) + ((long)j << 8) + i] * inv;
}
// tiled 33-tap seq-conv residual (OH already softmax-normalized)
__global__ void res_tile_kernel(const float* __restrict__ oh, const float* __restrict__ qkv,
                                const float* __restrict__ resk, float* __restrict__ aout) {
    __shared__ float sv[160][64];
    __shared__ float sw[33];
    int nb = blockIdx.x << 7;
    int h = blockIdx.y, b = blockIdx.z;
    int tid = threadIdx.x;
    if (tid < 33) sw[tid] = resk[h * 33 + tid];
    const float* vbase = qkv + (long)b * NPD * D3 + 2 * DD + h * DH;
    for (int i = tid; i < 160 * 64; i += 256) {
        int r = i >> 6, d = i & 63;
        long n = (long)nb + r - 16;
        sv[r][d] = (n >= 0 && n < NPD) ? vbase[n * D3 + d] : 0.f;
    }
    __syncthreads();
    int d = tid & 63, r0 = tid >> 6;
    const float* ohb = oh + ((long)(b * NH + h)) * NPD * DH;
    float* ab = aout + (long)b * NPD * DD + h * DH;
#pragma unroll 4
    for (int p = 0; p < 32; p++) {
        int nl = p * 4 + r0;
        long n = nb + nl;
        float acc = ohb[n * DH + d];
#pragma unroll
        for (int j = 0; j < 33; j++) acc += sw[j] * sv[nl + j][d];
        ab[n * DD + d] = acc;
    }
}
__global__ void wt_kernel(const float* k7, const float* k5, const float* k3, float* wt) {
    int idx = blockIdx.x * 256 + threadIdx.x;
    if (idx >= 49 * DD) return;
    int o = idx / DD, c = idx - o * DD;
    int dy = o / 7, dx = o - dy * 7;
    float w = k7[c * 49 + o];
    if (dy >= 1 && dy <= 5 && dx >= 1 && dx <= 5) w += k5[c * 25 + (dy-1)*5 + (dx-1)];
    if (dy >= 2 && dy <= 4 && dx >= 2 && dx <= 4) w += k3[c * 9 + (dy-2)*3 + (dx-2)];
    if (dy == 3 && dx == 3) w += 1.f;
    wt[o * DD + c] = w;
}
#define PPEG_SMEM ((22*22*64 + 49*64) * 4)
__global__ void __launch_bounds__(256)
ppeg_tile_kernel(const float* __restrict__ H, const float* __restrict__ wt,
                 const float* __restrict__ b7, const float* __restrict__ b5,
                 const float* __restrict__ b3, float* __restrict__ H2) {
    extern __shared__ float ps[];
    float* sw = ps;
    float* sv = ps + 49 * 64;
    int tile = blockIdx.x;
    int ty0 = (tile >> 3) << 4, tx0 = (tile & 7) << 4;
    int cg = blockIdx.y << 6;
    int b = blockIdx.z;
    int tid = threadIdx.x;
    const float* img = H + ((long)b * NC + 1) * DD;
    for (int i = tid; i < 49 * 64; i += 256)
        sw[i] = wt[(i >> 6) * DD + cg + (i & 63)];
    for (int i = tid; i < 22 * 22 * 64; i += 256) {
        int c = i & 63, pix = i >> 6;
        int yy = pix / 22, xx = pix - yy * 22;
        int gy = ty0 - 3 + yy, gx = tx0 - 3 + xx;
        sv[i] = ((unsigned)gy < 128u && (unsigned)gx < 128u)
                ? img[((long)((gy << 7) + gx)) * DD + cg + c] : 0.f;
    }
    __syncthreads();
    int c = tid & 63, q = tid >> 6;
    float bsum = __ldg(b7 + cg + c) + __ldg(b5 + cg + c) + __ldg(b3 + cg + c);
    for (int p = 0; p < 64; p++) {
        int pix = p * 4 + q;
        int y = pix >> 4, x = pix & 15;
        float acc = bsum;
#pragma unroll
        for (int dy = 0; dy < 7; dy++)
#pragma unroll
            for (int dx = 0; dx < 7; dx++)
                acc += sw[(dy * 7 + dx) * 64 + c] * sv[(((y + dy) * 22) + x + dx) * 64 + c];
        H2[((long)b * NC + 1 + ((ty0 + y) << 7) + tx0 + x) * DD + cg + c] = acc;
    }
}
__global__ void final_kernel(const float* __restrict__ H, const float* __restrict__ g,
                             const float* __restrict__ be, const float* __restrict__ W2,
                             const float* __restrict__ b2, float* __restrict__ out) {
    __shared__ float shm[32];
    int b = blockIdx.x;
    const float* row = H + (long)b * NC * DD;
    int c0 = threadIdx.x * 4;
    float4 v = *(const float4*)(row + c0);
    float mu = brsum(v.x + v.y + v.z + v.w, shm) * (1.f / DD);
    float d0 = v.x-mu, d1 = v.y-mu, d2 = v.z-mu, d3 = v.w-mu;
    float var = brsum(d0*d0 + d1*d1 + d2*d2 + d3*d3, shm) * (1.f / DD);
    float r = rsqrtf(var + 1e-5f);
    float4 gg = *(const float4*)(g + c0), bb = *(const float4*)(be + c0);
    float4 w = *(const float4*)(W2 + c0);
    float o = (d0*r*gg.x+bb.x)*w.x + (d1*r*gg.y+bb.y)*w.y +
              (d2*r*gg.z+bb.z)*w.z + (d3*r*gg.w+bb.w)*w.w;
    o = brsum(o, shm);
    if (threadIdx.x == 0) out[b] = o + b2[0];
}

static void attention(float* hbuf, float* base,
                      const __nv_bfloat16* wqkv_bf, const __nv_bfloat16* wout_bf,
                      const float* bout, const float* resk, const float* g, const float* be,
                      cudaStream_t s2, cudaEvent_t evA, cudaEvent_t evB)
{
    float *XLN = base+OFF_XLN, *QKV = base+OFF_QKV;
    float *OH = base+OFF_OH, *AOUT = base+OFF_AOUT;
    float *QL = base+OFF_QL, *KL = base+OFF_KL, *A2 = base+OFF_A2;
    float *Z0 = base+OFF_Z0, *Z1 = base+OFF_Z1, *XZ = base+OFF_XZ;
    float *T1 = base+OFF_T1, *T2 = base+OFF_T2, *AV = base+OFF_AV, *ZAV = base+OFF_ZAV;
    float *AVP = base+OFF_AVP, *M3 = base+OFF_M3, *S3 = base+OFF_S3;
    int* SC = (int*)(base + OFF_SC);
    const long s = (long)LM * LM;
    const long LMDH = (long)LM * DH;

    ln_kernel<<<BB * NC, 128>>>(hbuf, g, be, XLN);
    TG<false,false,false>(XLN, wqkv_bf, nullptr, QKV, NPD, D3, DD, DD, D3,
                          (long)NPD*DD, (long)NPD*D3, BB);
    landmark_kernel<<<dim3(LM, BB*NH), 64>>>(QKV, QL, KL);
    attn_sm_kernel<<<dim3(LM/64, BB*NH), 256>>>(QL, KL, A2, DH, (long)NH*LM*DH, LMDH, (long)LM*LM);

    // ---- fork pinv chain onto side stream (depends only on A2) ----
    cudaEventRecord(evA, 0);
    cudaStreamWaitEvent(s2, evA, 0);
    zero_sc_kernel<<<1, 32, 0, s2>>>(SC);
    pinv_norm_kernel<<<16, 256, 0, s2>>>(A2, SC, SC + 1);
    pinv_init_kernel<<<4096, 256, 0, s2>>>(A2, Z0, SC);
    for (int it = 0; it < 6; it++) {
        float* Zin = (it & 1) ? Z1 : Z0;
        float* Zout = (it & 1) ? Z0 : Z1;
        TG3<128>(A2, Zin, XZ, T1, LM, LM, LM, LM, LM, LM, s, s, s, 16, 1.f, 0.f, -1.f, 7.f, s2);
        TG3<128>(XZ, T1, T2, nullptr, LM, LM, LM, LM, LM, LM, s, s, s, 16, -1.f, 15.f, 0.f, 0.f, s2);
        TG3<128>(XZ, T2, T1, nullptr, LM, LM, LM, LM, LM, LM, s, s, s, 16, -1.f, 13.f, 0.f, 0.f, s2);
        TG3<128>(Zin, T1, Zout, nullptr, LM, LM, LM, LM, LM, LM, s, s, s, 16, 0.25f, 0.f, 0.f, 0.f, s2);
    }
    cudaEventRecord(evB, s2);

    // ---- main stream: fused flash attn3 -> AV ----
    cudaFuncSetAttribute(flash3, cudaFuncAttributeMaxDynamicSharedMemorySize, F3_SMEM);
    flash3<<<dim3(NSPL, 4, 16), 256, F3_SMEM>>>(QKV, QL, AVP, M3, S3);
    f3comb<<<16*LM*DH/256, 256>>>(AVP, M3, S3, AV);

    // ---- join: pinv result needed ----
    cudaStreamWaitEvent(0, evB, 0);
    TG3<64>(Z0, AV, ZAV, nullptr, LM, DH, LM, LM, DH, DH,
            s, LMDH, LMDH, 16, 1.f, 0.f, 0.f, 0.f, 0);
    cudaFuncSetAttribute(attn1oh, cudaFuncAttributeMaxDynamicSharedMemorySize, A1OH_SMEM);
    attn1oh<<<dim3(NPD/64, BB*NH), 256, A1OH_SMEM>>>(QKV, KL, ZAV, OH);
    res_tile_kernel<<<dim3(NPD/128, NH, BB), 256>>>(OH, QKV, resk, AOUT);
    TG<true,false,true>(AOUT, wout_bf, bout, hbuf, NPD, DD, DD, DD, DD,
                        (long)NPD*DD, (long)NC*DD, BB);
}

extern "C" void kernel_launch(void* const* d_in, const int* in_sizes, int n_in,
                              void* d_out, int out_size) {
    const float* features = (const float*)d_in[0];
    const float* W1    = (const float*)d_in[1];
    const float* b1    = (const float*)d_in[2];
    const float* cls   = (const float*)d_in[3];
    const float* ln1_g = (const float*)d_in[4];
    const float* ln1_b = (const float*)d_in[5];
    const float* Wqkv1 = (const float*)d_in[6];
    const float* Wout1 = (const float*)d_in[7];
    const float* bout1 = (const float*)d_in[8];
    const float* resk1 = (const float*)d_in[9];
    const float* ln2_g = (const float*)d_in[10];
    const float* ln2_b = (const float*)d_in[11];
    const float* Wqkv2 = (const float*)d_in[12];
    const float* Wout2 = (const float*)d_in[13];
    const float* bout2 = (const float*)d_in[14];
    const float* resk2 = (const float*)d_in[15];
    const float* k7    = (const float*)d_in[16];
    const float* b7c   = (const float*)d_in[17];
    const float* k5    = (const float*)d_in[18];
    const float* b5c   = (const float*)d_in[19];
    const float* k3    = (const float*)d_in[20];
    const float* b3c   = (const float*)d_in[21];
    const float* lnf_g = (const float*)d_in[22];
    const float* lnf_b = (const float*)d_in[23];
    const float* W2    = (const float*)d_in[24];
    const float* b2    = (const float*)d_in[25];

    float* base = nullptr;
    cudaGetSymbolAddress((void**)&base, g_buf);
    float* H = base + OFF_H;
    float* H2 = base + OFF_H2;
    float* XLN = base + OFF_XLN;
    __nv_bfloat16* wbf = (__nv_bfloat16*)(base + OFF_WBF);

    cudaStream_t s2;
    cudaStreamCreateWithFlags(&s2, cudaStreamNonBlocking);
    cudaEvent_t evA, evB;
    cudaEventCreateWithFlags(&evA, cudaEventDisableTiming);
    cudaEventCreateWithFlags(&evB, cudaEventDisableTiming);

    wprep<<<(int)((1536L*512 + 255) / 256), 256>>>(W1,    wbf + WB_T1,   IND, DD);
    wprep<<<(int)((512L*1536 + 255) / 256), 256>>>(Wqkv1, wbf + WB_QKV1, DD,  D3);
    wprep<<<(int)((512L*1536 + 255) / 256), 256>>>(Wqkv2, wbf + WB_QKV2, DD,  D3);
    wprep<<<(int)((512L*512  + 255) / 256), 256>>>(Wout1, wbf + WB_OUT1, DD,  DD);
    wprep<<<(int)((512L*512  + 255) / 256), 256>>>(Wout2, wbf + WB_OUT2, DD,  DD);
    wt_kernel<<<98, 256>>>(k7, k5, k3, base + OFF_WT);   // hoisted: overlaps FC1

    cls_kernel<<<4, 256>>>(H, cls);
    TG<true,true,false>(features, wbf + WB_T1, b1, H + DD, NTOK, DD, IND, IND, DD,
                        (long)NTOK*IND, (long)NC*DD, BB);
    zero_pads_kernel<<<1020, 256>>>(XLN);

    attention(H, base, wbf + WB_QKV1, wbf + WB_OUT1, bout1, resk1, ln1_g, ln1_b, s2, evA, evB);

    cudaFuncSetAttribute(ppeg_tile_kernel, cudaFuncAttributeMaxDynamicSharedMemorySize, PPEG_SMEM);
    ppeg_tile_kernel<<<dim3(64, 8, BB), 256, PPEG_SMEM>>>(H, base + OFF_WT, b7c, b5c, b3c, H2);
    h2cls_kernel<<<4, 256>>>(H, H2);

    attention(H2, base, wbf + WB_QKV2, wbf + WB_OUT2, bout2, resk2, ln2_g, ln2_b, s2, evA, evB);

    final_kernel<<<BB, 128>>>(H2, lnf_g, lnf_b, W2, b2, (float*)d_out);
}

// round 16
// speedup vs baseline: 1.1631x; 1.0184x over previous
#include <cuda_runtime.h>
#include <cuda_bf16.h>
#include <math.h>
#include <stdint.h>

#define BB 2
#define NTOK 16384
#define IND 1536
#define DD 512
#define NH 8
#define DH 64
#define LM 256
#define LCH 65
#define NPD 16640
#define NC 16385
#define PADN 255
#define D3 1536
#define QSCALE 0.125f
#define NSPL 10
#define KCH 1664    // NPD / NSPL

constexpr long SZ_H   = (long)BB*NC*DD;
constexpr long SZ_XLN = (long)BB*NPD*DD;   // bf16 hi+lo planes fit in this float region
constexpr long SZ_QKV = (long)BB*NPD*D3;
constexpr long SZ_OH  = (long)BB*NH*NPD*DH;
constexpr long SZ_MM  = 16L*LM*LM;
constexpr long SZ_SV  = 16L*LM*DH;

constexpr long OFF_H    = 0;
constexpr long OFF_XLN  = OFF_H    + SZ_H;
constexpr long OFF_QKV  = OFF_XLN  + SZ_XLN;
constexpr long OFF_OH   = OFF_QKV  + SZ_QKV;
constexpr long OFF_AOUT = OFF_OH   + SZ_OH;
constexpr long OFF_H2   = OFF_AOUT + SZ_XLN;
constexpr long OFF_QL   = OFF_H2   + SZ_XLN;
constexpr long OFF_KL   = OFF_QL   + SZ_SV;
constexpr long OFF_A2   = OFF_KL   + SZ_SV;
constexpr long OFF_Z0   = OFF_A2   + SZ_MM;
constexpr long OFF_Z1   = OFF_Z0   + SZ_MM;
constexpr long OFF_XZ   = OFF_Z1   + SZ_MM;
constexpr long OFF_T1   = OFF_XZ   + SZ_MM;
constexpr long OFF_T2   = OFF_T1   + SZ_MM;
constexpr long OFF_AV   = OFF_T2   + SZ_MM;
constexpr long OFF_ZAV  = OFF_AV   + SZ_SV;
constexpr long OFF_WT   = OFF_ZAV  + SZ_SV;
constexpr long OFF_AVP  = OFF_WT   + 49L*DD;
constexpr long OFF_SC   = OFF_AVP  + 16L*NSPL*LM*DH;
constexpr long OFF_M3   = OFF_SC   + 16;
constexpr long OFF_S3   = OFF_M3   + 16L*NSPL*LM;
constexpr long OFF_WBF  = OFF_S3   + 16L*NSPL*LM;
constexpr long WBF_FLOATS = 2900000;
constexpr long TOTAL_F  = OFF_WBF + WBF_FLOATS;

__device__ __align__(256) float g_buf[TOTAL_F];

constexpr long WB_T1   = 0;
constexpr long WB_QKV1 = WB_T1   + 2L*512*1536;
constexpr long WB_QKV2 = WB_QKV1 + 2L*512*1536;
constexpr long WB_OUT1 = WB_QKV2 + 2L*512*1536;
constexpr long WB_OUT2 = WB_OUT1 + 2L*512*512;

// ---------------- mma.sync m16n8k16 bf16 + ldmatrix ----------------
__device__ __forceinline__ void mma16816(float* c, const uint32_t* a, const uint32_t* b) {
    asm volatile(
        "mma.sync.aligned.m16n8k16.row.col.f32.bf16.bf16.f32 "
        "{%0,%1,%2,%3}, {%4,%5,%6,%7}, {%8,%9}, {%0,%1,%2,%3};"
        : "+f"(c[0]), "+f"(c[1]), "+f"(c[2]), "+f"(c[3])
        : "r"(a[0]), "r"(a[1]), "r"(a[2]), "r"(a[3]), "r"(b[0]), "r"(b[1]));
}
__device__ __forceinline__ void ldsm4(uint32_t& r0, uint32_t& r1, uint32_t& r2, uint32_t& r3,
                                      const void* p) {
    uint32_t a = (uint32_t)__cvta_generic_to_shared(p);
    asm volatile("ldmatrix.sync.aligned.m8n8.x4.shared.b16 {%0,%1,%2,%3}, [%4];"
        : "=r"(r0), "=r"(r1), "=r"(r2), "=r"(r3) : "r"(a));
}
__device__ __forceinline__ void ldsm4t(uint32_t& r0, uint32_t& r1, uint32_t& r2, uint32_t& r3,
                                       const void* p) {
    uint32_t a = (uint32_t)__cvta_generic_to_shared(p);
    asm volatile("ldmatrix.sync.aligned.m8n8.x4.trans.shared.b16 {%0,%1,%2,%3}, [%4];"
        : "=r"(r0), "=r"(r1), "=r"(r2), "=r"(r3) : "r"(a));
}
__device__ __forceinline__ void split2(float x0, float x1, uint32_t& hi, uint32_t& lo) {
    __nv_bfloat16 h0 = __float2bfloat16(x0), h1 = __float2bfloat16(x1);
    __nv_bfloat16 l0 = __float2bfloat16(x0 - __bfloat162float(h0));
    __nv_bfloat16 l1 = __float2bfloat16(x1 - __bfloat162float(h1));
    __nv_bfloat162 hh = __halves2bfloat162(h0, h1);
    __nv_bfloat162 ll = __halves2bfloat162(l0, l1);
    hi = *(uint32_t*)&hh; lo = *(uint32_t*)&ll;
}
__device__ __forceinline__ void split1(float x, __nv_bfloat16& h, __nv_bfloat16& l) {
    h = __float2bfloat16(x);
    l = __float2bfloat16(x - __bfloat162float(h));
}

// ============ weight GEMM: C = A[M,K] @ W[K,N] ============
// ABF: A supplied as pre-split bf16 hi/lo planes (Abh/Abl, stride lda in elements).
// RESID: C = H, rows >= PADN accumulate (fused residual).
template<bool BIASF, bool RELUF, bool RESID, bool ABF>
__global__ void __launch_bounds__(256)
tgemm(const float* __restrict__ A,
      const __nv_bfloat16* __restrict__ Abh, const __nv_bfloat16* __restrict__ Abl,
      const __nv_bfloat16* __restrict__ Wh, const __nv_bfloat16* __restrict__ Wl,
      const float* __restrict__ bias,
      float* __restrict__ C, int K, int lda, int ldc, long sAb, long sCb)
{
    __shared__ __nv_bfloat16 Ah[128][40], Al[128][40], Bh[128][40], Bl[128][40];
    const int tid = threadIdx.x, warp = tid >> 5, lane = tid & 31;
    const int rowBase = blockIdx.y << 7, colBase = blockIdx.x << 7;
    C += (long)blockIdx.z * sCb;
    const int lr = tid >> 1, lh = (tid & 1) << 4;
    const float* Ap = nullptr;
    const __nv_bfloat16 *Ahp = nullptr, *Alp = nullptr;
    if (ABF) {
        Ahp = Abh + (long)blockIdx.z * sAb + (long)(rowBase + lr) * lda + lh;
        Alp = Abl + (long)blockIdx.z * sAb + (long)(rowBase + lr) * lda + lh;
    } else {
        Ap = A + (long)blockIdx.z * sAb + (long)(rowBase + lr) * lda + lh;
    }
    const __nv_bfloat16* Bhp = Wh + (long)(colBase + lr) * K + lh;
    const __nv_bfloat16* Blp = Wl + (long)(colBase + lr) * K + lh;
    const int wm = (warp & 1) << 6, wn = (warp >> 1) << 5;
    const int gr = lane >> 2;
    const int a_r = (lane & 7) + ((lane >> 3) & 1) * 8;
    const int a_c = (lane >> 4) << 3;
    const int b_r = lane & 7;
    const int b_nj = (lane >> 4) & 1;
    const int b_c = ((lane >> 3) & 1) << 3;

    float acc[4][4][4];
#pragma unroll
    for (int i = 0; i < 4; i++)
#pragma unroll
        for (int j = 0; j < 4; j++)
#pragma unroll
            for (int t = 0; t < 4; t++) acc[i][j][t] = 0.f;

    float fa[16];
    uint4 vah0, vah1, val0, val1;
    uint4 vbh0, vbh1, vbl0, vbl1;
    if (ABF) {
        vah0 = *(const uint4*)(Ahp); vah1 = *(const uint4*)(Ahp + 8);
        val0 = *(const uint4*)(Alp); val1 = *(const uint4*)(Alp + 8);
    } else {
#pragma unroll
        for (int i = 0; i < 4; i++) {
            float4 v = *(const float4*)(Ap + i * 4);
            fa[i*4+0] = v.x; fa[i*4+1] = v.y; fa[i*4+2] = v.z; fa[i*4+3] = v.w;
        }
    }
    vbh0 = *(const uint4*)(Bhp); vbh1 = *(const uint4*)(Bhp + 8);
    vbl0 = *(const uint4*)(Blp); vbl1 = *(const uint4*)(Blp + 8);

    const int nch = K >> 5;
    for (int c = 0; c < nch; c++) {
        if (ABF) {
            *(uint4*)&Ah[lr][lh]     = vah0; *(uint4*)&Ah[lr][lh + 8] = vah1;
            *(uint4*)&Al[lr][lh]     = val0; *(uint4*)&Al[lr][lh + 8] = val1;
        } else {
#pragma unroll
            for (int i = 0; i < 8; i++) {
                uint32_t hi, lo;
                split2(fa[2*i], fa[2*i+1], hi, lo);
                *(uint32_t*)&Ah[lr][lh + 2*i] = hi;
                *(uint32_t*)&Al[lr][lh + 2*i] = lo;
            }
        }
        *(uint4*)&Bh[lr][lh]     = vbh0; *(uint4*)&Bh[lr][lh + 8] = vbh1;
        *(uint4*)&Bl[lr][lh]     = vbl0; *(uint4*)&Bl[lr][lh + 8] = vbl1;
        __syncthreads();
        if (c + 1 < nch) {
            if (ABF) {
                const __nv_bfloat16* ahp = Ahp + (c + 1) * 32;
                const __nv_bfloat16* alp = Alp + (c + 1) * 32;
                vah0 = *(const uint4*)(ahp); vah1 = *(const uint4*)(ahp + 8);
                val0 = *(const uint4*)(alp); val1 = *(const uint4*)(alp + 8);
            } else {
                const float* ap = Ap + (c + 1) * 32;
#pragma unroll
                for (int i = 0; i < 4; i++) {
                    float4 v = *(const float4*)(ap + i * 4);
                    fa[i*4+0] = v.x; fa[i*4+1] = v.y; fa[i*4+2] = v.z; fa[i*4+3] = v.w;
                }
            }
            const __nv_bfloat16* bp = Bhp + (c + 1) * 32;
            const __nv_bfloat16* lp = Blp + (c + 1) * 32;
            vbh0 = *(const uint4*)(bp); vbh1 = *(const uint4*)(bp + 8);
            vbl0 = *(const uint4*)(lp); vbl1 = *(const uint4*)(lp + 8);
        }
#pragma unroll
        for (int s = 0; s < 2; s++) {
            const int k16 = s * 16;
            uint32_t bhf[4][2], blf[4][2];
#pragma unroll
            for (int njp = 0; njp < 2; njp++) {
                int n = wn + (njp * 2 + b_nj) * 8 + b_r;
                ldsm4(bhf[njp*2][0], bhf[njp*2][1], bhf[njp*2+1][0], bhf[njp*2+1][1],
                      &Bh[n][k16 + b_c]);
                ldsm4(blf[njp*2][0], blf[njp*2][1], blf[njp*2+1][0], blf[njp*2+1][1],
                      &Bl[n][k16 + b_c]);
            }
#pragma unroll
            for (int mi = 0; mi < 4; mi++) {
                int r = wm + mi * 16 + a_r;
                uint32_t ah[4], al[4];
                ldsm4(ah[0], ah[1], ah[2], ah[3], &Ah[r][k16 + a_c]);
                ldsm4(al[0], al[1], al[2], al[3], &Al[r][k16 + a_c]);
#pragma unroll
                for (int nj = 0; nj < 4; nj++) {
                    mma16816(acc[mi][nj], ah, bhf[nj]);
                    mma16816(acc[mi][nj], ah, blf[nj]);
                    mma16816(acc[mi][nj], al, bhf[nj]);
                }
            }
        }
        __syncthreads();
    }

#pragma unroll
    for (int mi = 0; mi < 4; mi++) {
        int row = rowBase + wm + mi * 16 + gr;
#pragma unroll
        for (int nj = 0; nj < 4; nj++) {
            int col = colBase + wn + nj * 8 + (lane & 3) * 2;
            float v0 = acc[mi][nj][0], v1 = acc[mi][nj][1];
            float v2 = acc[mi][nj][2], v3 = acc[mi][nj][3];
            if (BIASF) {
                float b0 = __ldg(bias + col), b1 = __ldg(bias + col + 1);
                v0 += b0; v1 += b1; v2 += b0; v3 += b1;
            }
            if (RELUF) {
                v0 = fmaxf(v0, 0.f); v1 = fmaxf(v1, 0.f);
                v2 = fmaxf(v2, 0.f); v3 = fmaxf(v3, 0.f);
            }
            if (RESID) {
                if (row >= PADN) {
                    float* a0 = C + (long)(row - PADN) * ldc + col;
                    float2 o = *(float2*)a0;
                    *(float2*)a0 = make_float2(v0 + o.x, v1 + o.y);
                }
                if (row + 8 >= PADN) {
                    float* a1 = C + (long)(row + 8 - PADN) * ldc + col;
                    float2 o = *(float2*)a1;
                    *(float2*)a1 = make_float2(v2 + o.x, v3 + o.y);
                }
            } else {
                *(float2*)(C + (long)row * ldc + col)       = make_float2(v0, v1);
                *(float2*)(C + (long)(row + 8) * ldc + col) = make_float2(v2, v3);
            }
        }
    }
}

template<bool BI, bool RE, bool RD>
static void TG(const float* A, const __nv_bfloat16* wb, const float* bias, float* C,
               int M, int N, int K, int lda, int ldc, long sAb, long sCb, int nbz)
{
    dim3 g(N >> 7, M >> 7, nbz);
    tgemm<BI, RE, RD, false><<<g, 256>>>(A, nullptr, nullptr, wb, wb + (long)N * K,
                                         bias, C, K, lda, ldc, sAb, sCb);
}
template<bool BI, bool RE, bool RD>
static void TGB(const __nv_bfloat16* Abh, const __nv_bfloat16* Abl,
                const __nv_bfloat16* wb, const float* bias, float* C,
                int M, int N, int K, int lda, int ldc, long sAb, long sCb, int nbz)
{
    dim3 g(N >> 7, M >> 7, nbz);
    tgemm<BI, RE, RD, true><<<g, 256>>>(nullptr, Abh, Abl, wb, wb + (long)N * K,
                                        bias, C, K, lda, ldc, sAb, sCb);
}

// ============ natural-layout GEMM (pinv/ZAV): C = alpha*A@B + diag*I ============
template<int BN>
__global__ void __launch_bounds__(256)
tg3(const float* __restrict__ A, const float* __restrict__ B, float* __restrict__ C,
    float* __restrict__ C2, int K, int lda, int ldb, int ldc,
    long sA1, long sB1, long sC,
    float alpha, float addDiag, float alpha2, float diag2)
{
    __shared__ __nv_bfloat16 Ah[64][40], Al[64][40];
    __shared__ __nv_bfloat16 Bkh[32][BN + 8], Bkl[32][BN + 8];
    const int tid = threadIdx.x, warp = tid >> 5, lane = tid & 31;
    int z = blockIdx.z;
    A += (long)z * sA1;
    B += (long)z * sB1;
    C += (long)z * sC;
    if (C2) C2 += (long)z * sC;
    const int rowBase = blockIdx.y << 6, colBase = blockIdx.x * BN;
    const int lr = tid >> 2, lh = (tid & 3) << 3;
    const float* Ap = A + (long)(rowBase + lr) * lda + lh;
    constexpr int BNV = BN / 8;
    const int bkr = tid >> 3, bn0 = (tid & 7) * BNV;
    const float* Bp = B + (long)bkr * ldb + colBase + bn0;
    constexpr int NJ = BN / 32;
    const int wm = (warp & 1) << 5, wn = (warp >> 1) * (BN / 4);
    const int gr = lane >> 2;
    const int a_r = (lane & 7) + ((lane >> 3) & 1) * 8, a_c = (lane >> 4) << 3;
    const int b_kr = (lane & 7) + ((lane >> 3) & 1) * 8, b_nc = (lane >> 4) << 3;

    float acc[2][NJ][4];
#pragma unroll
    for (int i = 0; i < 2; i++)
#pragma unroll
        for (int j = 0; j < NJ; j++)
#pragma unroll
            for (int t = 0; t < 4; t++) acc[i][j][t] = 0.f;

    float fa[8], fb[BNV];
#pragma unroll
    for (int i = 0; i < 2; i++) {
        float4 v = *(const float4*)(Ap + i * 4);
        fa[i*4+0] = v.x; fa[i*4+1] = v.y; fa[i*4+2] = v.z; fa[i*4+3] = v.w;
    }
#pragma unroll
    for (int i = 0; i < BNV / 4; i++) {
        float4 v = *(const float4*)(Bp + i * 4);
        fb[i*4+0] = v.x; fb[i*4+1] = v.y; fb[i*4+2] = v.z; fb[i*4+3] = v.w;
    }

    const int nch = K >> 5;
    for (int c = 0; c < nch; c++) {
#pragma unroll
        for (int i = 0; i < 4; i++) {
            uint32_t hi, lo;
            split2(fa[2*i], fa[2*i+1], hi, lo);
            *(uint32_t*)&Ah[lr][lh + 2*i] = hi;
            *(uint32_t*)&Al[lr][lh + 2*i] = lo;
        }
#pragma unroll
        for (int i = 0; i < BNV / 2; i++) {
            uint32_t hi, lo;
            split2(fb[2*i], fb[2*i+1], hi, lo);
            *(uint32_t*)&Bkh[bkr][bn0 + 2*i] = hi;
            *(uint32_t*)&Bkl[bkr][bn0 + 2*i] = lo;
        }
        __syncthreads();
        if (c + 1 < nch) {
            const float* ap = Ap + (c + 1) * 32;
#pragma unroll
            for (int i = 0; i < 2; i++) {
                float4 v = *(const float4*)(ap + i * 4);
                fa[i*4+0] = v.x; fa[i*4+1] = v.y; fa[i*4+2] = v.z; fa[i*4+3] = v.w;
            }
            const float* bp = Bp + (long)(c + 1) * 32 * ldb;
#pragma unroll
            for (int i = 0; i < BNV / 4; i++) {
                float4 v = *(const float4*)(bp + i * 4);
                fb[i*4+0] = v.x; fb[i*4+1] = v.y; fb[i*4+2] = v.z; fb[i*4+3] = v.w;
            }
        }
#pragma unroll
        for (int s = 0; s < 2; s++) {
            const int k16 = s * 16;
            uint32_t bhf[NJ][2], blf[NJ][2];
#pragma unroll
            for (int njp = 0; njp < NJ / 2; njp++) {
                int n = wn + njp * 16 + b_nc;
                ldsm4t(bhf[njp*2][0], bhf[njp*2][1], bhf[njp*2+1][0], bhf[njp*2+1][1],
                       &Bkh[k16 + b_kr][n]);
                ldsm4t(blf[njp*2][0], blf[njp*2][1], blf[njp*2+1][0], blf[njp*2+1][1],
                       &Bkl[k16 + b_kr][n]);
            }
#pragma unroll
            for (int mi = 0; mi < 2; mi++) {
                int r = wm + mi * 16 + a_r;
                uint32_t ah[4], al[4];
                ldsm4(ah[0], ah[1], ah[2], ah[3], &Ah[r][k16 + a_c]);
                ldsm4(al[0], al[1], al[2], al[3], &Al[r][k16 + a_c]);
#pragma unroll
                for (int nj = 0; nj < NJ; nj++) {
                    mma16816(acc[mi][nj], ah, bhf[nj]);
                    mma16816(acc[mi][nj], ah, blf[nj]);
                    mma16816(acc[mi][nj], al, bhf[nj]);
                }
            }
        }
        __syncthreads();
    }

#pragma unroll
    for (int mi = 0; mi < 2; mi++) {
        int row = rowBase + wm + mi * 16 + gr;
#pragma unroll
        for (int nj = 0; nj < NJ; nj++) {
            int col = colBase + wn + nj * 8 + (lane & 3) * 2;
            float a0 = acc[mi][nj][0], a1 = acc[mi][nj][1];
            float a2 = acc[mi][nj][2], a3 = acc[mi][nj][3];
            float v0 = alpha * a0 + ((row == col)     ? addDiag : 0.f);
            float v1 = alpha * a1 + ((row == col + 1) ? addDiag : 0.f);
            float v2 = alpha * a2 + ((row + 8 == col)     ? addDiag : 0.f);
            float v3 = alpha * a3 + ((row + 8 == col + 1) ? addDiag : 0.f);
            *(float2*)(C + (long)row * ldc + col)       = make_float2(v0, v1);
            *(float2*)(C + (long)(row + 8) * ldc + col) = make_float2(v2, v3);
            if (C2) {
                float w0 = alpha2 * a0 + ((row == col)     ? diag2 : 0.f);
                float w1 = alpha2 * a1 + ((row == col + 1) ? diag2 : 0.f);
                float w2 = alpha2 * a2 + ((row + 8 == col)     ? diag2 : 0.f);
                float w3 = alpha2 * a3 + ((row + 8 == col + 1) ? diag2 : 0.f);
                *(float2*)(C2 + (long)row * ldc + col)       = make_float2(w0, w1);
                *(float2*)(C2 + (long)(row + 8) * ldc + col) = make_float2(w2, w3);
            }
        }
    }
}

template<int BN>
static void TG3(const float* A, const float* B, float* C, float* C2,
                int M, int N, int K, int lda, int ldb, int ldc,
                long sA1, long sB1, long sC, int nz,
                float alpha, float addDiag, float alpha2, float diag2, cudaStream_t st)
{
    dim3 g(N / BN, M >> 6, nz);
    tg3<BN><<<g, 256, 0, st>>>(A, B, C, C2, K, lda, ldb, ldc, sA1, sB1, sC,
                               alpha, addDiag, alpha2, diag2);
}

// ============ flash attn3 ============
#define F3_SMEM (8*9216 + 2048)
__global__ void __launch_bounds__(256)
flash3(const float* __restrict__ QKV, const float* __restrict__ QL,
       float* __restrict__ AVP, float* __restrict__ MM, float* __restrict__ SS)
{
    extern __shared__ char sm_[];
    __nv_bfloat16 (*Qh)[72] = (__nv_bfloat16(*)[72])(sm_);
    __nv_bfloat16 (*Qlw)[72] = (__nv_bfloat16(*)[72])(sm_ + 9216);
    __nv_bfloat16 (*Kh)[72] = (__nv_bfloat16(*)[72])(sm_ + 18432);
    __nv_bfloat16 (*Kl)[72] = (__nv_bfloat16(*)[72])(sm_ + 27648);
    __nv_bfloat16 (*Vh)[72] = (__nv_bfloat16(*)[72])(sm_ + 36864);
    __nv_bfloat16 (*Vl)[72] = (__nv_bfloat16(*)[72])(sm_ + 46080);
    __nv_bfloat16 (*Ph)[72] = (__nv_bfloat16(*)[72])(sm_ + 55296);
    __nv_bfloat16 (*Pl)[72] = (__nv_bfloat16(*)[72])(sm_ + 64512);
    float* red = (float*)(sm_ + 73728);
    const int tid = threadIdx.x, warp = tid >> 5, lane = tid & 31;
    const int l2 = lane & 3, gr = lane >> 2;
    const int ns = blockIdx.x, rb = blockIdx.y, z = blockIdx.z;
    const int b = z >> 3, h = z & 7;
    const int wm = (warp & 1) << 5, cg = warp >> 1, wn = cg << 4;
    const int a_r = (lane & 7) + ((lane >> 3) & 1) * 8, a_c = (lane >> 4) << 3;
    const int b_r = lane & 7, b_nj = (lane >> 4) & 1, b_c = ((lane >> 3) & 1) << 3;
    const int b_kr = (lane & 7) + ((lane >> 3) & 1) * 8, b_nc = (lane >> 4) << 3;
    const int lr = tid >> 2, lh = (tid & 3) << 4;

    {
        const float* qp = QL + (long)z * LM * DH + (long)(rb * 64 + lr) * DH + lh;
#pragma unroll
        for (int i = 0; i < 4; i++) {
            float4 v = *(const float4*)(qp + i * 4);
            uint32_t hi, lo;
            split2(v.x, v.y, hi, lo);
            *(uint32_t*)&Qh[lr][lh + i*4]     = hi; *(uint32_t*)&Qlw[lr][lh + i*4]     = lo;
            split2(v.z, v.w, hi, lo);
            *(uint32_t*)&Qh[lr][lh + i*4 + 2] = hi; *(uint32_t*)&Qlw[lr][lh + i*4 + 2] = lo;
        }
    }
    float accav[2][2][4];
    float mrun[2][2], srun[2][2];
#pragma unroll
    for (int i = 0; i < 2; i++)
#pragma unroll
        for (int t = 0; t < 2; t++) { mrun[i][t] = -3.0e38f; srun[i][t] = 0.f; }
#pragma unroll
    for (int i = 0; i < 2; i++)
#pragma unroll
        for (int j = 0; j < 2; j++)
#pragma unroll
            for (int t = 0; t < 4; t++) accav[i][j][t] = 0.f;

    const float* kvb = QKV + (long)b * NPD * D3 + h * DH;
    for (int c = 0; c < 26; c++) {
        long tb = (long)ns * KCH + c * 64;
        {
            const float* kp = kvb + (tb + lr) * D3 + DD + lh;
            const float* vp = kvb + (tb + lr) * D3 + 2 * DD + lh;
#pragma unroll
            for (int i = 0; i < 4; i++) {
                float4 v = *(const float4*)(kp + i * 4);
                uint32_t hi, lo;
                split2(v.x, v.y, hi, lo);
                *(uint32_t*)&Kh[lr][lh + i*4]     = hi; *(uint32_t*)&Kl[lr][lh + i*4]     = lo;
                split2(v.z, v.w, hi, lo);
                *(uint32_t*)&Kh[lr][lh + i*4 + 2] = hi; *(uint32_t*)&Kl[lr][lh + i*4 + 2] = lo;
                float4 w = *(const float4*)(vp + i * 4);
                split2(w.x, w.y, hi, lo);
                *(uint32_t*)&Vh[lr][lh + i*4]     = hi; *(uint32_t*)&Vl[lr][lh + i*4]     = lo;
                split2(w.z, w.w, hi, lo);
                *(uint32_t*)&Vh[lr][lh + i*4 + 2] = hi; *(uint32_t*)&Vl[lr][lh + i*4 + 2] = lo;
            }
        }
        __syncthreads();
        float acc[2][2][4];
#pragma unroll
        for (int i = 0; i < 2; i++)
#pragma unroll
            for (int j = 0; j < 2; j++)
#pragma unroll
                for (int t = 0; t < 4; t++) acc[i][j][t] = 0.f;
#pragma unroll
        for (int s = 0; s < 4; s++) {
            const int k16 = s * 16;
            uint32_t bhf[2][2], blf[2][2];
            {
                int n = wn + b_nj * 8 + b_r;
                ldsm4(bhf[0][0], bhf[0][1], bhf[1][0], bhf[1][1], &Kh[n][k16 + b_c]);
                ldsm4(blf[0][0], blf[0][1], blf[1][0], blf[1][1], &Kl[n][k16 + b_c]);
            }
#pragma unroll
            for (int mi = 0; mi < 2; mi++) {
                int r = wm + mi * 16 + a_r;
                uint32_t ah[4], al[4];
                ldsm4(ah[0], ah[1], ah[2], ah[3], &Qh[r][k16 + a_c]);
                ldsm4(al[0], al[1], al[2], al[3], &Qlw[r][k16 + a_c]);
#pragma unroll
                for (int nj = 0; nj < 2; nj++) {
                    mma16816(acc[mi][nj], ah, bhf[nj]);
                    mma16816(acc[mi][nj], ah, blf[nj]);
                    mma16816(acc[mi][nj], al, bhf[nj]);
                }
            }
        }
#pragma unroll
        for (int mi = 0; mi < 2; mi++)
#pragma unroll
            for (int nj = 0; nj < 2; nj++)
#pragma unroll
                for (int t = 0; t < 4; t++) acc[mi][nj][t] *= QSCALE;
#pragma unroll
        for (int mi = 0; mi < 2; mi++)
#pragma unroll
            for (int t = 0; t < 2; t++) {
                float m = fmaxf(fmaxf(acc[mi][0][2*t], acc[mi][0][2*t+1]),
                                fmaxf(acc[mi][1][2*t], acc[mi][1][2*t+1]));
                m = fmaxf(m, __shfl_xor_sync(0xffffffffu, m, 1));
                m = fmaxf(m, __shfl_xor_sync(0xffffffffu, m, 2));
                red[(wm + mi * 16 + gr + t * 8) * 4 + cg] = m;
            }
        __syncthreads();
#pragma unroll
        for (int mi = 0; mi < 2; mi++)
#pragma unroll
            for (int t = 0; t < 2; t++) {
                const float* r4 = red + (wm + mi * 16 + gr + t * 8) * 4;
                float mc = fmaxf(fmaxf(r4[0], r4[1]), fmaxf(r4[2], r4[3]));
                float mnew = fmaxf(mrun[mi][t], mc);
                float f = __expf(mrun[mi][t] - mnew);
                mrun[mi][t] = mnew;
                float sc = 0.f;
#pragma unroll
                for (int nj = 0; nj < 2; nj++) {
                    float e0 = __expf(acc[mi][nj][2*t]   - mnew);
                    float e1 = __expf(acc[mi][nj][2*t+1] - mnew);
                    acc[mi][nj][2*t] = e0; acc[mi][nj][2*t+1] = e1;
                    sc += e0 + e1;
                    accav[mi][nj][2*t] *= f; accav[mi][nj][2*t+1] *= f;
                }
                sc += __shfl_xor_sync(0xffffffffu, sc, 1);
                sc += __shfl_xor_sync(0xffffffffu, sc, 2);
                srun[mi][t] = srun[mi][t] * f + sc;
                int row = wm + mi * 16 + gr + t * 8;
#pragma unroll
                for (int nj = 0; nj < 2; nj++) {
                    int col = wn + nj * 8 + l2 * 2;
                    uint32_t hi, lo;
                    split2(acc[mi][nj][2*t], acc[mi][nj][2*t+1], hi, lo);
                    *(uint32_t*)&Ph[row][col] = hi;
                    *(uint32_t*)&Pl[row][col] = lo;
                }
            }
        __syncthreads();
#pragma unroll
        for (int s = 0; s < 4; s++) {
            const int k16 = s * 16;
            uint32_t bhf[2][2], blf[2][2];
            ldsm4t(bhf[0][0], bhf[0][1], bhf[1][0], bhf[1][1], &Vh[k16 + b_kr][wn + b_nc]);
            ldsm4t(blf[0][0], blf[0][1], blf[1][0], blf[1][1], &Vl[k16 + b_kr][wn + b_nc]);
#pragma unroll
            for (int mi = 0; mi < 2; mi++) {
                int r = wm + mi * 16 + a_r;
                uint32_t ah[4], al[4];
                ldsm4(ah[0], ah[1], ah[2], ah[3], &Ph[r][k16 + a_c]);
                ldsm4(al[0], al[1], al[2], al[3], &Pl[r][k16 + a_c]);
#pragma unroll
                for (int nj = 0; nj < 2; nj++) {
                    mma16816(accav[mi][nj], ah, bhf[nj]);
                    mma16816(accav[mi][nj], ah, blf[nj]);
                    mma16816(accav[mi][nj], al, bhf[nj]);
                }
            }
        }
        __syncthreads();
    }

#pragma unroll
    for (int mi = 0; mi < 2; mi++)
#pragma unroll
        for (int t = 0; t < 2; t++) {
            if (l2 == 0) red[(wm + mi * 16 + gr + t * 8) * 4 + cg] = srun[mi][t];
        }
    __syncthreads();
    float* avp = AVP + (((long)z * NSPL + ns) * LM + rb * 64) * DH;
#pragma unroll
    for (int mi = 0; mi < 2; mi++)
#pragma unroll
        for (int t = 0; t < 2; t++) {
            int row = wm + mi * 16 + gr + t * 8;
#pragma unroll
            for (int nj = 0; nj < 2; nj++) {
                int col = wn + nj * 8 + l2 * 2;
                *(float2*)(avp + (long)row * DH + col) =
                    make_float2(accav[mi][nj][2*t], accav[mi][nj][2*t+1]);
            }
            if (cg == 0 && l2 == 0) {
                const float* r4 = red + row * 4;
                long mi_idx = ((long)z * NSPL + ns) * LM + rb * 64 + row;
                MM[mi_idx] = mrun[mi][t];
                SS[mi_idx] = r4[0] + r4[1] + r4[2] + r4[3];
            }
        }
}

__global__ void f3comb(const float* __restrict__ AVP, const float* __restrict__ MM,
                       const float* __restrict__ SS, float* __restrict__ AV)
{
    int idx = blockIdx.x * 256 + threadIdx.x;
    int z = idx >> 14, r = (idx >> 6) & 255, d = idx & 63;
    long mbase = (long)z * NSPL * LM + r;
    float m = -3.0e38f;
#pragma unroll
    for (int ns = 0; ns < NSPL; ns++) m = fmaxf(m, __ldg(MM + mbase + (long)ns * LM));
    float s = 0.f, a = 0.f;
#pragma unroll
    for (int ns = 0; ns < NSPL; ns++) {
        float e = __expf(__ldg(MM + mbase + (long)ns * LM) - m);
        s += __ldg(SS + mbase + (long)ns * LM) * e;
        a += __ldg(AVP + ((long)(z * NSPL + ns) * LM + r) * DH + d) * e;
    }
    AV[idx] = a / s;
}

// ============ fused attn1 + softmax + @ZAV ============
#define A1OH_SMEM 76800
__global__ void __launch_bounds__(256)
attn1oh(const float* __restrict__ QKV, const float* __restrict__ KL,
        const float* __restrict__ ZAV, float* __restrict__ OH)
{
    extern __shared__ char sm_[];
    const int tid = threadIdx.x, warp = tid >> 5, lane = tid & 31;
    const int l2 = lane & 3, gr = lane >> 2;
    int z = blockIdx.y, b = z >> 3, h = z & 7;
    const int rowBase = blockIdx.x << 6;
    const float* Qp = QKV + (long)b * NPD * D3 + h * DH;
    KL += (long)z * LM * DH;
    ZAV += (long)z * LM * DH;
    OH += (long)z * NPD * DH;
    const int a_r = (lane & 7) + ((lane >> 3) & 1) * 8, a_c = (lane >> 4) << 3;
    const int b_r = lane & 7, b_nj = (lane >> 4) & 1, b_c = ((lane >> 3) & 1) << 3;

    const int rg = warp & 1, cg = warp >> 1;
    const int wm1 = rg << 5, wn1 = cg << 6;
    __nv_bfloat16 (*Ah)[40] = (__nv_bfloat16(*)[40])(sm_);
    __nv_bfloat16 (*Al)[40] = (__nv_bfloat16(*)[40])(sm_ + 5120);
    __nv_bfloat16 (*Bh)[40] = (__nv_bfloat16(*)[40])(sm_ + 10240);
    __nv_bfloat16 (*Bl)[40] = (__nv_bfloat16(*)[40])(sm_ + 30720);

    float acc[2][8][4];
#pragma unroll
    for (int i = 0; i < 2; i++)
#pragma unroll
        for (int j = 0; j < 8; j++)
#pragma unroll
            for (int t = 0; t < 4; t++) acc[i][j][t] = 0.f;

    const int lr = tid >> 2, lh = (tid & 3) << 3;
    for (int c = 0; c < 2; c++) {
        const float* ap = Qp + (long)(rowBase + lr) * D3 + c * 32 + lh;
#pragma unroll
        for (int i = 0; i < 2; i++) {
            float4 v = *(const float4*)(ap + i * 4);
            uint32_t hi, lo;
            split2(v.x, v.y, hi, lo);
            *(uint32_t*)&Ah[lr][lh + i*4]     = hi; *(uint32_t*)&Al[lr][lh + i*4]     = lo;
            split2(v.z, v.w, hi, lo);
            *(uint32_t*)&Ah[lr][lh + i*4 + 2] = hi; *(uint32_t*)&Al[lr][lh + i*4 + 2] = lo;
        }
        const float* bp = KL + (long)tid * DH + c * 32;
#pragma unroll
        for (int i = 0; i < 8; i++) {
            float4 v = *(const float4*)(bp + i * 4);
            uint32_t hi, lo;
            split2(v.x, v.y, hi, lo);
            *(uint32_t*)&Bh[tid][i*4]     = hi; *(uint32_t*)&Bl[tid][i*4]     = lo;
            split2(v.z, v.w, hi, lo);
            *(uint32_t*)&Bh[tid][i*4 + 2] = hi; *(uint32_t*)&Bl[tid][i*4 + 2] = lo;
        }
        __syncthreads();
#pragma unroll
        for (int s = 0; s < 2; s++) {
            const int k16 = s * 16;
            uint32_t bhf[8][2], blf[8][2];
#pragma unroll
            for (int njp = 0; njp < 4; njp++) {
                int n = wn1 + (njp * 2 + b_nj) * 8 + b_r;
                ldsm4(bhf[njp*2][0], bhf[njp*2][1], bhf[njp*2+1][0], bhf[njp*2+1][1],
                      &Bh[n][k16 + b_c]);
                ldsm4(blf[njp*2][0], blf[njp*2][1], blf[njp*2+1][0], blf[njp*2+1][1],
                      &Bl[n][k16 + b_c]);
            }
#pragma unroll
            for (int mi = 0; mi < 2; mi++) {
                int r = wm1 + mi * 16 + a_r;
                uint32_t ah[4], al[4];
                ldsm4(ah[0], ah[1], ah[2], ah[3], &Ah[r][k16 + a_c]);
                ldsm4(al[0], al[1], al[2], al[3], &Al[r][k16 + a_c]);
#pragma unroll
                for (int nj = 0; nj < 8; nj++) {
                    mma16816(acc[mi][nj], ah, bhf[nj]);
                    mma16816(acc[mi][nj], ah, blf[nj]);
                    mma16816(acc[mi][nj], al, bhf[nj]);
                }
            }
        }
        __syncthreads();
    }

#pragma unroll
    for (int i = 0; i < 2; i++)
#pragma unroll
        for (int j = 0; j < 8; j++)
#pragma unroll
            for (int t = 0; t < 4; t++) acc[i][j][t] *= QSCALE;

    float* red = (float*)sm_;
    float gmax[2][2], ginv[2][2];
#pragma unroll
    for (int mi = 0; mi < 2; mi++)
#pragma unroll
        for (int t = 0; t < 2; t++) {
            float m = -3.0e38f;
#pragma unroll
            for (int nj = 0; nj < 8; nj++)
                m = fmaxf(m, fmaxf(acc[mi][nj][2*t], acc[mi][nj][2*t+1]));
            m = fmaxf(m, __shfl_xor_sync(0xffffffffu, m, 1));
            m = fmaxf(m, __shfl_xor_sync(0xffffffffu, m, 2));
            red[(wm1 + mi * 16 + gr + t * 8) * 4 + cg] = m;
        }
    __syncthreads();
#pragma unroll
    for (int mi = 0; mi < 2; mi++)
#pragma unroll
        for (int t = 0; t < 2; t++) {
            const float* r4 = red + (wm1 + mi * 16 + gr + t * 8) * 4;
            gmax[mi][t] = fmaxf(fmaxf(r4[0], r4[1]), fmaxf(r4[2], r4[3]));
        }
    __syncthreads();
    float* red2 = red + 64 * 4;
#pragma unroll
    for (int mi = 0; mi < 2; mi++)
#pragma unroll
        for (int t = 0; t < 2; t++) {
            float s = 0.f;
#pragma unroll
            for (int nj = 0; nj < 8; nj++) {
                float e0 = __expf(acc[mi][nj][2*t]   - gmax[mi][t]);
                float e1 = __expf(acc[mi][nj][2*t+1] - gmax[mi][t]);
                acc[mi][nj][2*t] = e0; acc[mi][nj][2*t+1] = e1;
                s += e0 + e1;
            }
            s += __shfl_xor_sync(0xffffffffu, s, 1);
            s += __shfl_xor_sync(0xffffffffu, s, 2);
            red2[(wm1 + mi * 16 + gr + t * 8) * 4 + cg] = s;
        }
    __syncthreads();
#pragma unroll
    for (int mi = 0; mi < 2; mi++)
#pragma unroll
        for (int t = 0; t < 2; t++) {
            const float* r4 = red2 + (wm1 + mi * 16 + gr + t * 8) * 4;
            ginv[mi][t] = 1.f / (r4[0] + r4[1] + r4[2] + r4[3]);
        }
    __syncthreads();

    __nv_bfloat16 (*Ph)[264] = (__nv_bfloat16(*)[264])(sm_);
    __nv_bfloat16 (*Pl)[264] = (__nv_bfloat16(*)[264])(sm_ + 33792);
#pragma unroll
    for (int mi = 0; mi < 2; mi++)
#pragma unroll
        for (int t = 0; t < 2; t++) {
            int row = wm1 + mi * 16 + gr + t * 8;
#pragma unroll
            for (int nj = 0; nj < 8; nj++) {
                int col = wn1 + nj * 8 + l2 * 2;
                uint32_t hi, lo;
                split2(acc[mi][nj][2*t] * ginv[mi][t], acc[mi][nj][2*t+1] * ginv[mi][t], hi, lo);
                *(uint32_t*)&Ph[row][col] = hi;
                *(uint32_t*)&Pl[row][col] = lo;
            }
        }
    __syncthreads();

    const int wm3 = (warp & 1) << 5, wn3 = (warp >> 1) << 4;
    __nv_bfloat16 (*Bzh)[72] = (__nv_bfloat16(*)[72])(sm_ + 67584);
    __nv_bfloat16 (*Bzl)[72] = (__nv_bfloat16(*)[72])(sm_ + 67584 + 4608);
    const int zr = tid >> 3, zc = (tid & 7) << 3;
    float oacc[2][2][4];
#pragma unroll
    for (int i = 0; i < 2; i++)
#pragma unroll
        for (int j = 0; j < 2; j++)
#pragma unroll
            for (int t = 0; t < 4; t++) oacc[i][j][t] = 0.f;

    for (int kc = 0; kc < 8; kc++) {
        const float* zp = ZAV + (long)(kc * 32 + zr) * DH + zc;
#pragma unroll
        for (int i = 0; i < 2; i++) {
            float4 v = *(const float4*)(zp + i * 4);
            uint32_t hi, lo;
            split2(v.x, v.y, hi, lo);
            *(uint32_t*)&Bzh[zr][zc + i*4]     = hi; *(uint32_t*)&Bzl[zr][zc + i*4]     = lo;
            split2(v.z, v.w, hi, lo);
            *(uint32_t*)&Bzh[zr][zc + i*4 + 2] = hi; *(uint32_t*)&Bzl[zr][zc + i*4 + 2] = lo;
        }
        __syncthreads();
#pragma unroll
        for (int s = 0; s < 2; s++) {
            const int k16l = s * 16, k16g = kc * 32 + s * 16;
            uint32_t bhf[2][2], blf[2][2];
            ldsm4t(bhf[0][0], bhf[0][1], bhf[1][0], bhf[1][1],
                   &Bzh[k16l + (lane & 7) + ((lane >> 3) & 1) * 8][wn3 + ((lane >> 4) << 3)]);
            ldsm4t(blf[0][0], blf[0][1], blf[1][0], blf[1][1],
                   &Bzl[k16l + (lane & 7) + ((lane >> 3) & 1) * 8][wn3 + ((lane >> 4) << 3)]);
#pragma unroll
            for (int mi = 0; mi < 2; mi++) {
                int r = wm3 + mi * 16 + a_r;
                uint32_t ah[4], al[4];
                ldsm4(ah[0], ah[1], ah[2], ah[3], &Ph[r][k16g + a_c]);
                ldsm4(al[0], al[1], al[2], al[3], &Pl[r][k16g + a_c]);
#pragma unroll
                for (int nj = 0; nj < 2; nj++) {
                    mma16816(oacc[mi][nj], ah, bhf[nj]);
                    mma16816(oacc[mi][nj], ah, blf[nj]);
                    mma16816(oacc[mi][nj], al, bhf[nj]);
                }
            }
        }
        __syncthreads();
    }

#pragma unroll
    for (int mi = 0; mi < 2; mi++) {
        long row = rowBase + wm3 + mi * 16 + gr;
#pragma unroll
        for (int nj = 0; nj < 2; nj++) {
            int col = wn3 + nj * 8 + l2 * 2;
            *(float2*)(OH + row * DH + col)       = make_float2(oacc[mi][nj][0], oacc[mi][nj][1]);
            *(float2*)(OH + (row + 8) * DH + col) = make_float2(oacc[mi][nj][2], oacc[mi][nj][3]);
        }
    }
}

// weight prep
__global__ void wprep(const float* __restrict__ W, __nv_bfloat16* __restrict__ out, int K, int N) {
    long idx = (long)blockIdx.x * 256 + threadIdx.x;
    if (idx >= (long)K * N) return;
    int n = (int)(idx / K), k = (int)(idx - (long)n * K);
    float v = __ldg(W + (long)k * N + n);
    __nv_bfloat16 h = __float2bfloat16(v);
    out[idx] = h;
    out[(long)N * K + idx] = __float2bfloat16(v - __bfloat162float(h));
}

// ---------------- helpers ----------------
template<int V>
__device__ __forceinline__ void ldv(float* r, const float* __restrict__ p) {
    if constexpr (V == 2) { float2 t = *(const float2*)p; r[0]=t.x; r[1]=t.y; }
    else if constexpr (V == 4) { float4 t = *(const float4*)p; r[0]=t.x; r[1]=t.y; r[2]=t.z; r[3]=t.w; }
    else if constexpr (V == 8) { ldv<4>(r, p); ldv<4>(r + 4, p + 4); }
}
__device__ __forceinline__ float brsum(float v, float* shm) {
    int lane = threadIdx.x & 31, wid = threadIdx.x >> 5;
#pragma unroll
    for (int o = 16; o; o >>= 1) v += __shfl_xor_sync(0xffffffffu, v, o);
    __syncthreads();
    if (lane == 0) shm[wid] = v;
    __syncthreads();
    int nw = blockDim.x >> 5;
    float r = (threadIdx.x < nw) ? shm[threadIdx.x] : 0.f;
    if (wid == 0) {
#pragma unroll
        for (int o = 16; o; o >>= 1) r += __shfl_xor_sync(0xffffffffu, r, o);
        if (lane == 0) shm[0] = r;
    }
    __syncthreads();
    return shm[0];
}

// ---------------- fused GEMM + row softmax (attn2 only) ----------------
__global__ void __launch_bounds__(256)
attn_sm_kernel(const float* __restrict__ A, const float* __restrict__ B,
               float* __restrict__ C, int lda, long sAb, long sAh, long sCz)
{
    int z = blockIdx.y, b = z >> 3, h = z & 7;
    A += (long)b * sAb + (long)h * sAh;
    B += (long)z * (LM * DH);
    C += (long)z * sCz;
    __shared__ float As[2][8][64];
    __shared__ float Bs[2][8][256];
    const int tid = threadIdx.x, tx = tid & 15, ty = tid >> 4;
    const int rowBase = blockIdx.x * 64;
    const int arow = tid >> 2, acol = (tid & 3) * 2;
    const float* Ap = A + (long)(rowBase + arow) * lda + acol;
    const float* Bp = B + tid * DH;
    float ra[2], rb[8];
    float acc[4][16];
#pragma unroll
    for (int i = 0; i < 4; i++)
#pragma unroll
        for (int j = 0; j < 16; j++) acc[i][j] = 0.f;

    ldv<2>(ra, Ap);
    ldv<8>(rb, Bp);
    As[0][acol][arow] = ra[0]; As[0][acol + 1][arow] = ra[1];
#pragma unroll
    for (int i = 0; i < 8; i++) Bs[0][i][tid] = rb[i];
    __syncthreads();

    for (int kb = 0; kb < 8; kb++) {
        int cur = kb & 1;
        if (kb + 1 < 8) { ldv<2>(ra, Ap + (kb + 1) * 8); ldv<8>(rb, Bp + (kb + 1) * 8); }
#pragma unroll
        for (int k = 0; k < 8; k++) {
            float a[4], bv[16];
#pragma unroll
            for (int i = 0; i < 4; i++) a[i] = As[cur][k][ty * 4 + i];
#pragma unroll
            for (int j = 0; j < 16; j++) bv[j] = Bs[cur][k][tx * 16 + j];
#pragma unroll
            for (int i = 0; i < 4; i++)
#pragma unroll
                for (int j = 0; j < 16; j++) acc[i][j] += a[i] * bv[j];
        }
        if (kb + 1 < 8) {
            int nxt = cur ^ 1;
            As[nxt][acol][arow] = ra[0]; As[nxt][acol + 1][arow] = ra[1];
#pragma unroll
            for (int i = 0; i < 8; i++) Bs[nxt][i][tid] = rb[i];
        }
        __syncthreads();
    }

#pragma unroll
    for (int i = 0; i < 4; i++) {
        float m = -3.0e38f;
#pragma unroll
        for (int j = 0; j < 16; j++) { acc[i][j] *= QSCALE; m = fmaxf(m, acc[i][j]); }
#pragma unroll
        for (int o = 8; o; o >>= 1) m = fmaxf(m, __shfl_xor_sync(0xffffffffu, m, o));
        float s = 0.f;
#pragma unroll
        for (int j = 0; j < 16; j++) { float e = __expf(acc[i][j] - m); acc[i][j] = e; s += e; }
#pragma unroll
        for (int o = 8; o; o >>= 1) s += __shfl_xor_sync(0xffffffffu, s, o);
        float inv = 1.f / s;
        int row = rowBase + ty * 4 + i;
        float* crow = C + (long)row * LM + tx * 16;
#pragma unroll
        for (int j = 0; j < 16; j += 4) {
            float4 o = make_float4(acc[i][j] * inv, acc[i][j+1] * inv, acc[i][j+2] * inv, acc[i][j+3] * inv);
            *(float4*)(crow + j) = o;
        }
    }
}

// ---------------- small kernels ----------------
__global__ void cls_kernel(float* H, const float* cls) {
    int i = blockIdx.x * 256 + threadIdx.x;
    if (i >= BB * DD) return;
    int b = i / DD, c = i - b * DD;
    H[(long)b * NC * DD + c] = cls[c];
}
__global__ void h2cls_kernel(const float* __restrict__ H, float* __restrict__ H2) {
    int i = blockIdx.x * 256 + threadIdx.x;
    if (i >= BB * DD) return;
    int b = i / DD, c = i - b * DD;
    H2[(long)b * NC * DD + c] = H[(long)b * NC * DD + c];
}
// zero both bf16 pad planes
__global__ void zero_pads_kernel(__nv_bfloat16* xh, __nv_bfloat16* xl) {
    int idx = blockIdx.x * 256 + threadIdx.x;     // BB*PADN*DD
    int b = idx / (PADN * DD), r = idx - b * (PADN * DD);
    long o = (long)b * NPD * DD + r;
    xh[o] = __float2bfloat16(0.f);
    xl[o] = __float2bfloat16(0.f);
}
// LN -> bf16 hi/lo planes
__global__ void ln_kernel(const float* __restrict__ H, const float* __restrict__ g,
                          const float* __restrict__ be,
                          __nv_bfloat16* __restrict__ xh, __nv_bfloat16* __restrict__ xl) {
    __shared__ float shm[32];
    int t = blockIdx.x, b = t / NC, tt = t - b * NC;
    const float* row = H + ((long)b * NC + tt) * DD;
    long obase = ((long)b * NPD + PADN + tt) * DD;
    int c0 = threadIdx.x * 4;
    float4 v = *(const float4*)(row + c0);
    float mu = brsum(v.x + v.y + v.z + v.w, shm) * (1.f / DD);
    float d0 = v.x-mu, d1 = v.y-mu, d2 = v.z-mu, d3 = v.w-mu;
    float var = brsum(d0*d0 + d1*d1 + d2*d2 + d3*d3, shm) * (1.f / DD);
    float r = rsqrtf(var + 1e-5f);
    float4 gg = *(const float4*)(g + c0), bb = *(const float4*)(be + c0);
    float o0 = d0*r*gg.x+bb.x, o1 = d1*r*gg.y+bb.y, o2 = d2*r*gg.z+bb.z, o3 = d3*r*gg.w+bb.w;
    uint32_t h01, l01, h23, l23;
    split2(o0, o1, h01, l01);
    split2(o2, o3, h23, l23);
    *(uint2*)(xh + obase + c0) = make_uint2(h01, h23);
    *(uint2*)(xl + obase + c0) = make_uint2(l01, l23);
}
__global__ void landmark_kernel(const float* __restrict__ qkv, float* __restrict__ ql,
                                float* __restrict__ kl) {
    int i = blockIdx.x, z = blockIdx.y, d = threadIdx.x;
    int b = z >> 3, h = z & 7;
    const float* base = qkv + (long)b * NPD * D3 + (long)i * LCH * D3 + h * DH + d;
    float sq = 0.f, sk = 0.f;
    for (int j = 0; j < LCH; j++) { sq += base[(long)j * D3]; sk += base[(long)j * D3 + DD]; }
    ql[((long)z * LM + i) * DH + d] = sq * (1.f / LCH);
    kl[((long)z * LM + i) * DH + d] = sk * (1.f / LCH);
}
__global__ void zero_sc_kernel(int* sc) { if (threadIdx.x < 2) sc[threadIdx.x] = 0; }
__global__ void pinv_norm_kernel(const float* __restrict__ a2, int* mr, int* mc) {
    int z = blockIdx.x, t = threadIdx.x;
    const float* A = a2 + (long)z * LM * LM;
    float rs = 0.f, cs = 0.f;
    for (int j = 0; j < LM; j++) { rs += A[t * LM + j]; cs += A[j * LM + t]; }
    atomicMax(mr, __float_as_int(rs));
    atomicMax(mc, __float_as_int(cs));
}
__global__ void pinv_init_kernel(const float* __restrict__ a2, float* __restrict__ z0,
                                 const int* __restrict__ sc) {
    float inv = 1.f / (__int_as_float(sc[0]) * __int_as_float(sc[1]));
    long idx = (long)blockIdx.x * 256 + threadIdx.x;
    long zz = idx >> 16;
    int i = (int)((idx >> 8) & 255), j = (int)(idx & 255);
    z0[idx] = a2[(zz << 16) + ((long)j << 8) + i] * inv;
}
// tiled 33-tap seq-conv residual -> AOUT bf16 hi/lo planes
__global__ void res_tile_kernel(const float* __restrict__ oh, const float* __restrict__ qkv,
                                const float* __restrict__ resk,
                                __nv_bfloat16* __restrict__ aoh, __nv_bfloat16* __restrict__ aol) {
    __shared__ float sv[160][64];
    __shared__ float sw[33];
    int nb = blockIdx.x << 7;
    int h = blockIdx.y, b = blockIdx.z;
    int tid = threadIdx.x;
    if (tid < 33) sw[tid] = resk[h * 33 + tid];
    const float* vbase = qkv + (long)b * NPD * D3 + 2 * DD + h * DH;
    for (int i = tid; i < 160 * 64; i += 256) {
        int r = i >> 6, d = i & 63;
        long n = (long)nb + r - 16;
        sv[r][d] = (n >= 0 && n < NPD) ? vbase[n * D3 + d] : 0.f;
    }
    __syncthreads();
    int d = tid & 63, r0 = tid >> 6;
    const float* ohb = oh + ((long)(b * NH + h)) * NPD * DH;
    long abase = (long)b * NPD * DD + h * DH + d;
#pragma unroll 4
    for (int p = 0; p < 32; p++) {
        int nl = p * 4 + r0;
        long n = nb + nl;
        float acc = ohb[n * DH + d];
#pragma unroll
        for (int j = 0; j < 33; j++) acc += sw[j] * sv[nl + j][d];
        __nv_bfloat16 hh, ll;
        split1(acc, hh, ll);
        aoh[abase + n * DD] = hh;
        aol[abase + n * DD] = ll;
    }
}
__global__ void wt_kernel(const float* k7, const float* k5, const float* k3, float* wt) {
    int idx = blockIdx.x * 256 + threadIdx.x;
    if (idx >= 49 * DD) return;
    int o = idx / DD, c = idx - o * DD;
    int dy = o / 7, dx = o - dy * 7;
    float w = k7[c * 49 + o];
    if (dy >= 1 && dy <= 5 && dx >= 1 && dx <= 5) w += k5[c * 25 + (dy-1)*5 + (dx-1)];
    if (dy >= 2 && dy <= 4 && dx >= 2 && dx <= 4) w += k3[c * 9 + (dy-2)*3 + (dx-2)];
    if (dy == 3 && dx == 3) w += 1.f;
    wt[o * DD + c] = w;
}
#define PPEG_SMEM ((22*22*64 + 49*64) * 4)
__global__ void __launch_bounds__(256)
ppeg_tile_kernel(const float* __restrict__ H, const float* __restrict__ wt,
                 const float* __restrict__ b7, const float* __restrict__ b5,
                 const float* __restrict__ b3, float* __restrict__ H2) {
    extern __shared__ float ps[];
    float* sw = ps;
    float* sv = ps + 49 * 64;
    int tile = blockIdx.x;
    int ty0 = (tile >> 3) << 4, tx0 = (tile & 7) << 4;
    int cg = blockIdx.y << 6;
    int b = blockIdx.z;
    int tid = threadIdx.x;
    const float* img = H + ((long)b * NC + 1) * DD;
    for (int i = tid; i < 49 * 64; i += 256)
        sw[i] = wt[(i >> 6) * DD + cg + (i & 63)];
    for (int i = tid; i < 22 * 22 * 64; i += 256) {
        int c = i & 63, pix = i >> 6;
        int yy = pix / 22, xx = pix - yy * 22;
        int gy = ty0 - 3 + yy, gx = tx0 - 3 + xx;
        sv[i] = ((unsigned)gy < 128u && (unsigned)gx < 128u)
                ? img[((long)((gy << 7) + gx)) * DD + cg + c] : 0.f;
    }
    __syncthreads();
    int c = tid & 63, q = tid >> 6;
    float bsum = __ldg(b7 + cg + c) + __ldg(b5 + cg + c) + __ldg(b3 + cg + c);
    for (int p = 0; p < 64; p++) {
        int pix = p * 4 + q;
        int y = pix >> 4, x = pix & 15;
        float acc = bsum;
#pragma unroll
        for (int dy = 0; dy < 7; dy++)
#pragma unroll
            for (int dx = 0; dx < 7; dx++)
                acc += sw[(dy * 7 + dx) * 64 + c] * sv[(((y + dy) * 22) + x + dx) * 64 + c];
        H2[((long)b * NC + 1 + ((ty0 + y) << 7) + tx0 + x) * DD + cg + c] = acc;
    }
}
__global__ void final_kernel(const float* __restrict__ H, const float* __restrict__ g,
                             const float* __restrict__ be, const float* __restrict__ W2,
                             const float* __restrict__ b2, float* __restrict__ out) {
    __shared__ float shm[32];
    int b = blockIdx.x;
    const float* row = H + (long)b * NC * DD;
    int c0 = threadIdx.x * 4;
    float4 v = *(const float4*)(row + c0);
    float mu = brsum(v.x + v.y + v.z + v.w, shm) * (1.f / DD);
    float d0 = v.x-mu, d1 = v.y-mu, d2 = v.z-mu, d3 = v.w-mu;
    float var = brsum(d0*d0 + d1*d1 + d2*d2 + d3*d3, shm) * (1.f / DD);
    float r = rsqrtf(var + 1e-5f);
    float4 gg = *(const float4*)(g + c0), bb = *(const float4*)(be + c0);
    float4 w = *(const float4*)(W2 + c0);
    float o = (d0*r*gg.x+bb.x)*w.x + (d1*r*gg.y+bb.y)*w.y +
              (d2*r*gg.z+bb.z)*w.z + (d3*r*gg.w+bb.w)*w.w;
    o = brsum(o, shm);
    if (threadIdx.x == 0) out[b] = o + b2[0];
}

static void attention(float* hbuf, float* base,
                      const __nv_bfloat16* wqkv_bf, const __nv_bfloat16* wout_bf,
                      const float* bout, const float* resk, const float* g, const float* be,
                      cudaStream_t s2, cudaEvent_t evA, cudaEvent_t evB)
{
    __nv_bfloat16* XLNh = (__nv_bfloat16*)(base + OFF_XLN);
    __nv_bfloat16* XLNl = XLNh + SZ_XLN;
    __nv_bfloat16* AOh  = (__nv_bfloat16*)(base + OFF_AOUT);
    __nv_bfloat16* AOl  = AOh + SZ_XLN;
    float *QKV = base+OFF_QKV;
    float *OH = base+OFF_OH;
    float *QL = base+OFF_QL, *KL = base+OFF_KL, *A2 = base+OFF_A2;
    float *Z0 = base+OFF_Z0, *Z1 = base+OFF_Z1, *XZ = base+OFF_XZ;
    float *T1 = base+OFF_T1, *T2 = base+OFF_T2, *AV = base+OFF_AV, *ZAV = base+OFF_ZAV;
    float *AVP = base+OFF_AVP, *M3 = base+OFF_M3, *S3 = base+OFF_S3;
    int* SC = (int*)(base + OFF_SC);
    const long s = (long)LM * LM;
    const long LMDH = (long)LM * DH;

    ln_kernel<<<BB * NC, 128>>>(hbuf, g, be, XLNh, XLNl);
    TGB<false,false,false>(XLNh, XLNl, wqkv_bf, nullptr, QKV, NPD, D3, DD, DD, D3,
                           (long)NPD*DD, (long)NPD*D3, BB);
    landmark_kernel<<<dim3(LM, BB*NH), 64>>>(QKV, QL, KL);
    attn_sm_kernel<<<dim3(LM/64, BB*NH), 256>>>(QL, KL, A2, DH, (long)NH*LM*DH, LMDH, (long)LM*LM);

    // ---- fork pinv chain onto side stream (depends only on A2) ----
    cudaEventRecord(evA, 0);
    cudaStreamWaitEvent(s2, evA, 0);
    zero_sc_kernel<<<1, 32, 0, s2>>>(SC);
    pinv_norm_kernel<<<16, 256, 0, s2>>>(A2, SC, SC + 1);
    pinv_init_kernel<<<4096, 256, 0, s2>>>(A2, Z0, SC);
    for (int it = 0; it < 6; it++) {
        float* Zin = (it & 1) ? Z1 : Z0;
        float* Zout = (it & 1) ? Z0 : Z1;
        TG3<128>(A2, Zin, XZ, T1, LM, LM, LM, LM, LM, LM, s, s, s, 16, 1.f, 0.f, -1.f, 7.f, s2);
        TG3<128>(XZ, T1, T2, nullptr, LM, LM, LM, LM, LM, LM, s, s, s, 16, -1.f, 15.f, 0.f, 0.f, s2);
        TG3<128>(XZ, T2, T1, nullptr, LM, LM, LM, LM, LM, LM, s, s, s, 16, -1.f, 13.f, 0.f, 0.f, s2);
        TG3<128>(Zin, T1, Zout, nullptr, LM, LM, LM, LM, LM, LM, s, s, s, 16, 0.25f, 0.f, 0.f, 0.f, s2);
    }
    cudaEventRecord(evB, s2);

    // ---- main stream: fused flash attn3 -> AV ----
    cudaFuncSetAttribute(flash3, cudaFuncAttributeMaxDynamicSharedMemorySize, F3_SMEM);
    flash3<<<dim3(NSPL, 4, 16), 256, F3_SMEM>>>(QKV, QL, AVP, M3, S3);
    f3comb<<<16*LM*DH/256, 256>>>(AVP, M3, S3, AV);

    // ---- join: pinv result needed ----
    cudaStreamWaitEvent(0, evB, 0);
    TG3<64>(Z0, AV, ZAV, nullptr, LM, DH, LM, LM, DH, DH,
            s, LMDH, LMDH, 16, 1.f, 0.f, 0.f, 0.f, 0);
    cudaFuncSetAttribute(attn1oh, cudaFuncAttributeMaxDynamicSharedMemorySize, A1OH_SMEM);
    attn1oh<<<dim3(NPD/64, BB*NH), 256, A1OH_SMEM>>>(QKV, KL, ZAV, OH);
    res_tile_kernel<<<dim3(NPD/128, NH, BB), 256>>>(OH, QKV, resk, AOh, AOl);
    TGB<true,false,true>(AOh, AOl, wout_bf, bout, hbuf, NPD, DD, DD, DD, DD,
                         (long)NPD*DD, (long)NC*DD, BB);
}

extern "C" void kernel_launch(void* const* d_in, const int* in_sizes, int n_in,
                              void* d_out, int out_size) {
    const float* features = (const float*)d_in[0];
    const float* W1    = (const float*)d_in[1];
    const float* b1    = (const float*)d_in[2];
    const float* cls   = (const float*)d_in[3];
    const float* ln1_g = (const float*)d_in[4];
    const float* ln1_b = (const float*)d_in[5];
    const float* Wqkv1 = (const float*)d_in[6];
    const float* Wout1 = (const float*)d_in[7];
    const float* bout1 = (const float*)d_in[8];
    const float* resk1 = (const float*)d_in[9];
    const float* ln2_g = (const float*)d_in[10];
    const float* ln2_b = (const float*)d_in[11];
    const float* Wqkv2 = (const float*)d_in[12];
    const float* Wout2 = (const float*)d_in[13];
    const float* bout2 = (const float*)d_in[14];
    const float* resk2 = (const float*)d_in[15];
    const float* k7    = (const float*)d_in[16];
    const float* b7c   = (const float*)d_in[17];
    const float* k5    = (const float*)d_in[18];
    const float* b5c   = (const float*)d_in[19];
    const float* k3    = (const float*)d_in[20];
    const float* b3c   = (const float*)d_in[21];
    const float* lnf_g = (const float*)d_in[22];
    const float* lnf_b = (const float*)d_in[23];
    const float* W2    = (const float*)d_in[24];
    const float* b2    = (const float*)d_in[25];

    float* base = nullptr;
    cudaGetSymbolAddress((void**)&base, g_buf);
    float* H = base + OFF_H;
    float* H2 = base + OFF_H2;
    __nv_bfloat16* XLNh = (__nv_bfloat16*)(base + OFF_XLN);
    __nv_bfloat16* XLNl = XLNh + SZ_XLN;
    __nv_bfloat16* wbf = (__nv_bfloat16*)(base + OFF_WBF);

    cudaStream_t s2;
    cudaStreamCreateWithFlags(&s2, cudaStreamNonBlocking);
    cudaEvent_t evA, evB;
    cudaEventCreateWithFlags(&evA, cudaEventDisableTiming);
    cudaEventCreateWithFlags(&evB, cudaEventDisableTiming);

    wprep<<<(int)((1536L*512 + 255) / 256), 256>>>(W1,    wbf + WB_T1,   IND, DD);
    wprep<<<(int)((512L*1536 + 255) / 256), 256>>>(Wqkv1, wbf + WB_QKV1, DD,  D3);
    wprep<<<(int)((512L*1536 + 255) / 256), 256>>>(Wqkv2, wbf + WB_QKV2, DD,  D3);
    wprep<<<(int)((512L*512  + 255) / 256), 256>>>(Wout1, wbf + WB_OUT1, DD,  DD);
    wprep<<<(int)((512L*512  + 255) / 256), 256>>>(Wout2, wbf + WB_OUT2, DD,  DD);
    wt_kernel<<<98, 256>>>(k7, k5, k3, base + OFF_WT);   // hoisted: overlaps FC1

    cls_kernel<<<4, 256>>>(H, cls);
    TG<true,true,false>(features, wbf + WB_T1, b1, H + DD, NTOK, DD, IND, IND, DD,
                        (long)NTOK*IND, (long)NC*DD, BB);
    zero_pads_kernel<<<1020, 256>>>(XLNh, XLNl);

    attention(H, base, wbf + WB_QKV1, wbf + WB_OUT1, bout1, resk1, ln1_g, ln1_b, s2, evA, evB);

    cudaFuncSetAttribute(ppeg_tile_kernel, cudaFuncAttributeMaxDynamicSharedMemorySize, PPEG_SMEM);
    ppeg_tile_kernel<<<dim3(64, 8, BB), 256, PPEG_SMEM>>>(H, base + OFF_WT, b7c, b5c, b3c, H2);
    h2cls_kernel<<<4, 256>>>(H, H2);

    attention(H2, base, wbf + WB_QKV2, wbf + WB_OUT2, bout2, resk2, ln2_g, ln2_b, s2, evA, evB);

    final_kernel<<<BB, 128>>>(H2, lnf_g, lnf_b, W2, b2, (float*)d_out);
}